// round 5
// baseline (speedup 1.0000x reference)
#include <cuda_runtime.h>
#include <cstdint>

typedef unsigned long long ull;

#define L_SEQ   1024
#define BATCH   2
#define DMODEL  1024
#define DI      2048
#define NSTATE  16
#define DTRANK  64

// ---------------- scratch (device globals: allocation-free) ----------------
__device__ float g_xz[4u * L_SEQ * 2 * DI];        // [dir*2+b][l][4096]  (xi | z), direction-local time
__device__ float g_xc[4u * L_SEQ * DI];            // [db][l][d]   conv+silu output (u)
__device__ float g_wxpad[2u * 128 * DI];           // padded+permuted Wx (B/C interleaved)
__device__ float g_xdbl_part[2u * 8 * (BATCH*L_SEQ) * 128];
__device__ float g_xdbl[2u * (BATCH*L_SEQ) * 128]; // cols 0..63 dt-rank, 64+2n=B[n], 65+2n=C[n]
__device__ float g_dt[4u * L_SEQ * DI];            // softplus(dt)
__device__ float g_y[4u * L_SEQ * DI];             // scan output, later gated in place
__device__ float g_opart[4u * (BATCH*L_SEQ) * DMODEL]; // [dir][ksplit] partial out

// ---------------- helpers ----------------
__device__ __forceinline__ ull pk2(float lo, float hi) {
    ull r; asm("mov.b64 %0, {%1,%2};" : "=l"(r) : "f"(lo), "f"(hi)); return r;
}
__device__ __forceinline__ void unpk(ull v, float& lo, float& hi) {
    asm("mov.b64 {%0,%1}, %2;" : "=f"(lo), "=f"(hi) : "l"(v));
}
__device__ __forceinline__ void fma2(ull& d, ull a, ull b) {
    asm("fma.rn.f32x2 %0, %1, %2, %0;" : "+l"(d) : "l"(a), "l"(b));
}
__device__ __forceinline__ float ex2f(float x) {
    float r; asm("ex2.approx.f32 %0, %1;" : "=f"(r) : "f"(x)); return r;
}
__device__ __forceinline__ float softplusf(float v) {
    return v > 20.f ? v : log1pf(expf(v));
}
__device__ __forceinline__ float siluf(float v) {
    return v / (1.f + __expf(-v));
}

// ---------------- generic f32x2 GEMM: C = A @ Bw^T (A: M x K rows, Bw: N x K rows) ---
// grid.x = N/128, grid.y = M/128, grid.z = K-split index.
// rev: remap A row (b*L + l) -> (b*L + (L-1-l))   (L = 1024 hardcoded)
// epi: 0 = store, 2 = softplus(v + bias[col])
__global__ void __launch_bounds__(256)
gemm_f2(const float* __restrict__ A, const float* __restrict__ Bw,
        float* __restrict__ C, int K, int lda, int ldb, int ldc,
        int rev, int epi, const float* __restrict__ bias, long long slab)
{
    __shared__ float As[8][132];
    __shared__ float Bs[8][132];

    const int tid = threadIdx.x;
    const int m0 = blockIdx.y * 128;
    const int n0 = blockIdx.x * 128;
    const float* Ap = A + (long long)blockIdx.z * K;
    const float* Bp = Bw + (long long)blockIdx.z * K;
    float* Cp = C + (long long)blockIdx.z * slab;

    const int lrow = tid >> 1;
    const int lk4  = (tid & 1) << 2;
    const int mg = m0 + lrow;
    const int arow = rev ? ((mg & ~(L_SEQ - 1)) | ((L_SEQ - 1) - (mg & (L_SEQ - 1)))) : mg;
    const float* aptr = Ap + (long long)arow * lda + lk4;
    const float* bptr = Bp + (long long)(n0 + lrow) * ldb + lk4;

    const int tx = tid & 15, ty = tid >> 4;

    ull acc[4][8];
    #pragma unroll
    for (int i = 0; i < 4; i++)
        #pragma unroll
        for (int j = 0; j < 8; j++) acc[i][j] = 0ull;

    float4 aReg = *(const float4*)aptr;
    float4 bReg = *(const float4*)bptr;
    const int KT = K >> 3;

    for (int kt = 0; kt < KT; ++kt) {
        As[lk4 + 0][lrow] = aReg.x; As[lk4 + 1][lrow] = aReg.y;
        As[lk4 + 2][lrow] = aReg.z; As[lk4 + 3][lrow] = aReg.w;
        Bs[lk4 + 0][lrow] = bReg.x; Bs[lk4 + 1][lrow] = bReg.y;
        Bs[lk4 + 2][lrow] = bReg.z; Bs[lk4 + 3][lrow] = bReg.w;
        __syncthreads();
        if (kt + 1 < KT) {
            aReg = *(const float4*)(aptr + (kt + 1) * 8);
            bReg = *(const float4*)(bptr + (kt + 1) * 8);
        }
        #pragma unroll
        for (int k = 0; k < 8; k++) {
            const ull* apr = (const ull*)&As[k][ty * 8];   // M-pairs come free (8B-aligned)
            ull a0 = apr[0], a1 = apr[1], a2 = apr[2], a3 = apr[3];
            float4 bv0 = *(const float4*)&Bs[k][tx * 8];
            float4 bv1 = *(const float4*)&Bs[k][tx * 8 + 4];
            float bb[8] = {bv0.x, bv0.y, bv0.z, bv0.w, bv1.x, bv1.y, bv1.z, bv1.w};
            #pragma unroll
            for (int j = 0; j < 8; j++) {
                ull bd = pk2(bb[j], bb[j]);
                fma2(acc[0][j], a0, bd);
                fma2(acc[1][j], a1, bd);
                fma2(acc[2][j], a2, bd);
                fma2(acc[3][j], a3, bd);
            }
        }
        __syncthreads();
    }

    // epilogue
    #pragma unroll
    for (int p = 0; p < 4; p++) {
        float lo[8], hi[8];
        #pragma unroll
        for (int j = 0; j < 8; j++) unpk(acc[p][j], lo[j], hi[j]);
        const int r0 = m0 + ty * 8 + p * 2;
        const int cn = n0 + tx * 8;
        if (epi == 2) {
            #pragma unroll
            for (int j = 0; j < 8; j++) {
                float bsv = bias[cn + j];
                lo[j] = softplusf(lo[j] + bsv);
                hi[j] = softplusf(hi[j] + bsv);
            }
        }
        float* c0 = Cp + (long long)r0 * ldc + cn;
        float* c1 = c0 + ldc;
        *(float4*)(c0)     = make_float4(lo[0], lo[1], lo[2], lo[3]);
        *(float4*)(c0 + 4) = make_float4(lo[4], lo[5], lo[6], lo[7]);
        *(float4*)(c1)     = make_float4(hi[0], hi[1], hi[2], hi[3]);
        *(float4*)(c1 + 4) = make_float4(hi[4], hi[5], hi[6], hi[7]);
    }
}

// ---------------- Wx pad+permute: row j<64 -> Wx[j]; 64+2n -> Wx[64+n](B); 65+2n -> Wx[80+n](C); >=96 -> 0
__global__ void wxpad_kernel(const float* __restrict__ Wx_f, const float* __restrict__ Wx_r)
{
    int idx = blockIdx.x * 256 + threadIdx.x;       // 2*128*2048 = 2^19
    int k = idx & (DI - 1);
    int j = (idx >> 11) & 127;
    int dir = idx >> 18;
    const float* Wx = dir ? Wx_r : Wx_f;
    float v = 0.f;
    if (j < 64) v = Wx[j * DI + k];
    else if (j < 96) {
        int nn = (j - 64) >> 1;
        int src = ((j - 64) & 1) ? (80 + nn) : (64 + nn);
        v = Wx[src * DI + k];
    }
    g_wxpad[idx] = v;
}

// ---------------- depthwise causal conv (K=4) + SiLU ----------------
__global__ void conv_silu_kernel(const float* __restrict__ Wc_f, const float* __restrict__ bc_f,
                                 const float* __restrict__ Wc_r, const float* __restrict__ bc_r)
{
    size_t idx = (size_t)blockIdx.x * 256 + threadIdx.x;   // 4*1024*2048 = 2^23
    int d  = (int)(idx & (DI - 1));
    int l  = (int)((idx >> 11) & (L_SEQ - 1));
    int db = (int)(idx >> 21);
    int dir = db >> 1;
    const float* Wc = dir ? Wc_r : Wc_f;
    const float* bc = dir ? bc_r : bc_f;
    const float4 w = *(const float4*)(Wc + d * 4);
    const float* base = g_xz + (size_t)db * L_SEQ * (2 * DI);
    float acc = bc[d];
    if (l >= 3) acc = fmaf(w.x, base[(size_t)(l - 3) * 4096 + d], acc);
    if (l >= 2) acc = fmaf(w.y, base[(size_t)(l - 2) * 4096 + d], acc);
    if (l >= 1) acc = fmaf(w.z, base[(size_t)(l - 1) * 4096 + d], acc);
    acc = fmaf(w.w, base[(size_t)l * 4096 + d], acc);
    g_xc[idx] = siluf(acc);
}

// ---------------- split-K reduce for x_dbl ----------------
__global__ void reduce_xdbl_kernel()
{
    int idx = blockIdx.x * 256 + threadIdx.x;       // 2*2048*128 = 2^19
    int dir = idx >> 18;
    int off = idx & ((1 << 18) - 1);
    const float* p = g_xdbl_part + (size_t)dir * 8 * (1 << 18) + off;
    float s = 0.f;
    #pragma unroll
    for (int s8 = 0; s8 < 8; s8++) s += p[(size_t)s8 * (1 << 18)];
    g_xdbl[idx] = s;
}

// ---------------- selective scan: warp = 4 channels x (8 lanes x 2 states) ----------------
__global__ void __launch_bounds__(256)
scan_kernel(const float* __restrict__ Alog_f, const float* __restrict__ Alog_r,
            const float* __restrict__ Dsk_f, const float* __restrict__ Dsk_r)
{
    int blk = blockIdx.x;           // 256 blocks: 64 per (dir,b)
    int db = blk >> 6;
    int dir = db >> 1;
    int dbase = (blk & 63) * 32;
    int lane = threadIdx.x & 31;
    int warp = threadIdx.x >> 5;
    int c4 = lane >> 3;
    int j  = lane & 7;              // state-pair index (n = 2j, 2j+1)
    int d = dbase + warp * 4 + c4;

    const float* Al = dir ? Alog_r : Alog_f;
    const float* Ds = dir ? Dsk_r : Dsk_f;
    const float* dtp = g_dt + (size_t)db * (L_SEQ * DI);
    const float* xcp = g_xc + (size_t)db * (L_SEQ * DI);
    const float* xdp = g_xdbl + (size_t)db * (L_SEQ * 128);
    float* yp = g_y + (size_t)db * (L_SEQ * DI);

    const float LOG2E = 1.4426950408889634f;
    float2 Ap = *(const float2*)(Al + d * NSTATE + 2 * j);
    float A0 = -__expf(Ap.x) * LOG2E;
    float A1 = -__expf(Ap.y) * LOG2E;
    float Dk = Ds[d];
    float h0 = 0.f, h1 = 0.f;

    float dt_c = dtp[d];
    float u_c  = xcp[d];
    float4 bc_c = *(const float4*)(xdp + 64 + 4 * j);   // B0,C0,B1,C1

    for (int t = 0; t < L_SEQ; ++t) {
        float dt_n = 0.f, u_n = 0.f; float4 bc_n = bc_c;
        if (t + 1 < L_SEQ) {
            dt_n = dtp[(size_t)(t + 1) * DI + d];
            u_n  = xcp[(size_t)(t + 1) * DI + d];
            bc_n = *(const float4*)(xdp + (size_t)(t + 1) * 128 + 64 + 4 * j);
        }
        float du = dt_c * u_c;
        h0 = fmaf(ex2f(dt_c * A0), h0, du * bc_c.x);
        h1 = fmaf(ex2f(dt_c * A1), h1, du * bc_c.z);
        float p = fmaf(h0, bc_c.y, h1 * bc_c.w);
        p += __shfl_xor_sync(0xffffffffu, p, 1);
        p += __shfl_xor_sync(0xffffffffu, p, 2);
        p += __shfl_xor_sync(0xffffffffu, p, 4);
        if (j == 0) yp[(size_t)t * DI + d] = fmaf(u_c, Dk, p);
        dt_c = dt_n; u_c = u_n; bc_c = bc_n;
    }
}

// ---------------- gating: y *= silu(z) ----------------
__global__ void gate_kernel()
{
    size_t idx = (size_t)blockIdx.x * 256 + threadIdx.x;   // 2^23
    int d  = (int)(idx & (DI - 1));
    int l  = (int)((idx >> 11) & (L_SEQ - 1));
    int db = (int)(idx >> 21);
    float z = g_xz[((size_t)db * L_SEQ + l) * 4096 + DI + d];
    g_y[idx] *= siluf(z);
}

// ---------------- final reduce: sum 4 partial slabs -> out ----------------
__global__ void reduce_out_kernel(float* __restrict__ out)
{
    int idx = blockIdx.x * 256 + threadIdx.x;       // 2048*1024 = 2^21
    const size_t S = (size_t)(BATCH * L_SEQ) * DMODEL;
    const float* p = g_opart + idx;
    out[idx] = (p[0] + p[S]) + (p[2 * S] + p[3 * S]);
}

// ---------------- launch ----------------
extern "C" void kernel_launch(void* const* d_in, const int* in_sizes, int n_in,
                              void* d_out, int out_size)
{
    (void)in_sizes; (void)n_in; (void)out_size;
    const float* x       = (const float*)d_in[0];
    const float* Win_f   = (const float*)d_in[1];
    const float* Wconv_f = (const float*)d_in[2];
    const float* bconv_f = (const float*)d_in[3];
    const float* Wx_f    = (const float*)d_in[4];
    const float* Wdt_f   = (const float*)d_in[5];
    const float* bdt_f   = (const float*)d_in[6];
    const float* Alog_f  = (const float*)d_in[7];
    const float* Dskip_f = (const float*)d_in[8];
    const float* Wout_f  = (const float*)d_in[9];
    const float* Win_r   = (const float*)d_in[10];
    const float* Wconv_r = (const float*)d_in[11];
    const float* bconv_r = (const float*)d_in[12];
    const float* Wx_r    = (const float*)d_in[13];
    const float* Wdt_r   = (const float*)d_in[14];
    const float* bdt_r   = (const float*)d_in[15];
    const float* Alog_r  = (const float*)d_in[16];
    const float* Dskip_r = (const float*)d_in[17];
    const float* Wout_r  = (const float*)d_in[18];
    float* out = (float*)d_out;

    float *xz, *xc, *wxpad, *xdblp, *xdbl, *dt, *y, *opart;
    cudaGetSymbolAddress((void**)&xz,    g_xz);
    cudaGetSymbolAddress((void**)&xc,    g_xc);
    cudaGetSymbolAddress((void**)&wxpad, g_wxpad);
    cudaGetSymbolAddress((void**)&xdblp, g_xdbl_part);
    cudaGetSymbolAddress((void**)&xdbl,  g_xdbl);
    cudaGetSymbolAddress((void**)&dt,    g_dt);
    cudaGetSymbolAddress((void**)&y,     g_y);
    cudaGetSymbolAddress((void**)&opart, g_opart);

    const long long XZ_DIR  = 2LL * L_SEQ * 2 * DI;      // 8388608
    const long long XC_DIR  = 2LL * L_SEQ * DI;          // 4194304
    const long long XDBL_DIR = 2048LL * 128;             // 262144
    const long long OUT_SLAB = 2048LL * DMODEL;          // 2097152

    // 1. pad+permute Wx
    wxpad_kernel<<<(2 * 128 * DI) / 256, 256>>>(Wx_f, Wx_r);

    // 2. in-projection (both dirs; rev handled by A-row remap)
    gemm_f2<<<dim3(32, 16, 1), 256>>>(x, Win_f, xz,          DMODEL, DMODEL, DMODEL, 2 * DI, 0, 0, nullptr, 0);
    gemm_f2<<<dim3(32, 16, 1), 256>>>(x, Win_r, xz + XZ_DIR, DMODEL, DMODEL, DMODEL, 2 * DI, 1, 0, nullptr, 0);

    // 3. depthwise conv + silu
    conv_silu_kernel<<<(4 * L_SEQ * DI) / 256, 256>>>(Wconv_f, bconv_f, Wconv_r, bconv_r);

    // 4. x_dbl = xc @ Wxpad^T   (split-K=8 -> partials -> reduce)
    gemm_f2<<<dim3(1, 16, 8), 256>>>(xc,          wxpad,            xdblp,                256, DI, DI, 128, 0, 0, nullptr, XDBL_DIR);
    gemm_f2<<<dim3(1, 16, 8), 256>>>(xc + XC_DIR, wxpad + 128 * DI, xdblp + 8 * XDBL_DIR, 256, DI, DI, 128, 0, 0, nullptr, XDBL_DIR);
    reduce_xdbl_kernel<<<(2 * 2048 * 128) / 256, 256>>>();

    // 5. dt = softplus(xdbl[:, :64] @ Wdt^T + bdt)
    gemm_f2<<<dim3(16, 16, 1), 256>>>(xdbl,            Wdt_f, dt,          DTRANK, 128, DTRANK, DI, 0, 2, bdt_f, 0);
    gemm_f2<<<dim3(16, 16, 1), 256>>>(xdbl + XDBL_DIR, Wdt_r, dt + XC_DIR, DTRANK, 128, DTRANK, DI, 0, 2, bdt_r, 0);

    // 6. selective scan
    scan_kernel<<<256, 256>>>(Alog_f, Alog_r, Dskip_f, Dskip_r);

    // 7. gating y *= silu(z)
    gate_kernel<<<(4 * L_SEQ * DI) / 256, 256>>>();

    // 8. out-projection (split-K=2 partials; rev reads y_r at reversed rows)
    gemm_f2<<<dim3(8, 16, 2), 256>>>(y,          Wout_f, opart,                1024, DI, DI, DMODEL, 0, 0, nullptr, OUT_SLAB);
    gemm_f2<<<dim3(8, 16, 2), 256>>>(y + XC_DIR, Wout_r, opart + 2 * OUT_SLAB, 1024, DI, DI, DMODEL, 1, 0, nullptr, OUT_SLAB);

    // 9. sum 4 partial slabs -> out
    reduce_out_kernel<<<(2048 * DMODEL) / 256, 256>>>(out);
}

// round 6
// speedup vs baseline: 1.0144x; 1.0144x over previous
#include <cuda_runtime.h>
#include <cstdint>

typedef unsigned long long ull;

#define L_SEQ   1024
#define BATCH   2
#define DMODEL  1024
#define DI      2048
#define NSTATE  16
#define DTRANK  64

// ---------------- scratch (device globals: allocation-free) ----------------
__device__ float g_xz[4u * L_SEQ * 2 * DI];        // [dir*2+b][l][4096]  (xi | z), direction-local time
__device__ float g_xc[4u * L_SEQ * DI];            // [db][l][d]   conv+silu output (u)
__device__ float g_wxpad[2u * 128 * DI];           // padded+permuted Wx (B/C interleaved)
__device__ float g_xdbl_part[2u * 8 * (BATCH*L_SEQ) * 128];
__device__ float g_xdbl[2u * (BATCH*L_SEQ) * 128]; // cols 0..63 dt-rank, 64+2n=B[n], 65+2n=C[n]
__device__ float g_dt[4u * L_SEQ * DI];            // softplus(dt)
__device__ float g_y[4u * L_SEQ * DI];             // scan output, later gated in place
__device__ float g_opart[4u * (BATCH*L_SEQ) * DMODEL]; // [dir][ksplit] partial out

// ---------------- helpers ----------------
__device__ __forceinline__ ull pk2(float lo, float hi) {
    ull r; asm("mov.b64 %0, {%1,%2};" : "=l"(r) : "f"(lo), "f"(hi)); return r;
}
__device__ __forceinline__ void unpk(ull v, float& lo, float& hi) {
    asm("mov.b64 {%0,%1}, %2;" : "=f"(lo), "=f"(hi) : "l"(v));
}
__device__ __forceinline__ void fma2(ull& d, ull a, ull b) {
    asm("fma.rn.f32x2 %0, %1, %2, %0;" : "+l"(d) : "l"(a), "l"(b));
}
__device__ __forceinline__ float ex2f(float x) {
    float r; asm("ex2.approx.f32 %0, %1;" : "=f"(r) : "f"(x)); return r;
}
__device__ __forceinline__ float softplusf(float v) {
    return v > 20.f ? v : log1pf(expf(v));
}
__device__ __forceinline__ float siluf(float v) {
    return v / (1.f + __expf(-v));
}

// ---------------- generic f32x2 GEMM: C = A @ Bw^T (A: M x K rows, Bw: N x K rows) ---
// grid.x = N/128, grid.y = M/128, grid.z = K-split index.
// rev: remap A row (b*L + l) -> (b*L + (L-1-l))   (L = 1024 hardcoded)
// epi: 0 = store, 2 = softplus(v + bias[col])
__global__ void __launch_bounds__(256)
gemm_f2(const float* __restrict__ A, const float* __restrict__ Bw,
        float* __restrict__ C, int K, int lda, int ldb, int ldc,
        int rev, int epi, const float* __restrict__ bias, long long slab)
{
    __shared__ float As[8][132];
    __shared__ float Bs[8][132];

    const int tid = threadIdx.x;
    const int m0 = blockIdx.y * 128;
    const int n0 = blockIdx.x * 128;
    const float* Ap = A + (long long)blockIdx.z * K;
    const float* Bp = Bw + (long long)blockIdx.z * K;
    float* Cp = C + (long long)blockIdx.z * slab;

    const int lrow = tid >> 1;
    const int lk4  = (tid & 1) << 2;
    const int mg = m0 + lrow;
    const int arow = rev ? ((mg & ~(L_SEQ - 1)) | ((L_SEQ - 1) - (mg & (L_SEQ - 1)))) : mg;
    const float* aptr = Ap + (long long)arow * lda + lk4;
    const float* bptr = Bp + (long long)(n0 + lrow) * ldb + lk4;

    const int tx = tid & 15, ty = tid >> 4;

    ull acc[4][8];
    #pragma unroll
    for (int i = 0; i < 4; i++)
        #pragma unroll
        for (int j = 0; j < 8; j++) acc[i][j] = 0ull;

    float4 aReg = *(const float4*)aptr;
    float4 bReg = *(const float4*)bptr;
    const int KT = K >> 3;

    for (int kt = 0; kt < KT; ++kt) {
        As[lk4 + 0][lrow] = aReg.x; As[lk4 + 1][lrow] = aReg.y;
        As[lk4 + 2][lrow] = aReg.z; As[lk4 + 3][lrow] = aReg.w;
        Bs[lk4 + 0][lrow] = bReg.x; Bs[lk4 + 1][lrow] = bReg.y;
        Bs[lk4 + 2][lrow] = bReg.z; Bs[lk4 + 3][lrow] = bReg.w;
        __syncthreads();
        if (kt + 1 < KT) {
            aReg = *(const float4*)(aptr + (kt + 1) * 8);
            bReg = *(const float4*)(bptr + (kt + 1) * 8);
        }
        #pragma unroll
        for (int k = 0; k < 8; k++) {
            const ull* apr = (const ull*)&As[k][ty * 8];   // M-pairs come free (8B-aligned)
            ull a0 = apr[0], a1 = apr[1], a2 = apr[2], a3 = apr[3];
            float4 bv0 = *(const float4*)&Bs[k][tx * 8];
            float4 bv1 = *(const float4*)&Bs[k][tx * 8 + 4];
            float bb[8] = {bv0.x, bv0.y, bv0.z, bv0.w, bv1.x, bv1.y, bv1.z, bv1.w};
            #pragma unroll
            for (int j = 0; j < 8; j++) {
                ull bd = pk2(bb[j], bb[j]);
                fma2(acc[0][j], a0, bd);
                fma2(acc[1][j], a1, bd);
                fma2(acc[2][j], a2, bd);
                fma2(acc[3][j], a3, bd);
            }
        }
        __syncthreads();
    }

    // epilogue
    #pragma unroll
    for (int p = 0; p < 4; p++) {
        float lo[8], hi[8];
        #pragma unroll
        for (int j = 0; j < 8; j++) unpk(acc[p][j], lo[j], hi[j]);
        const int r0 = m0 + ty * 8 + p * 2;
        const int cn = n0 + tx * 8;
        if (epi == 2) {
            #pragma unroll
            for (int j = 0; j < 8; j++) {
                float bsv = bias[cn + j];
                lo[j] = softplusf(lo[j] + bsv);
                hi[j] = softplusf(hi[j] + bsv);
            }
        }
        float* c0 = Cp + (long long)r0 * ldc + cn;
        float* c1 = c0 + ldc;
        *(float4*)(c0)     = make_float4(lo[0], lo[1], lo[2], lo[3]);
        *(float4*)(c0 + 4) = make_float4(lo[4], lo[5], lo[6], lo[7]);
        *(float4*)(c1)     = make_float4(hi[0], hi[1], hi[2], hi[3]);
        *(float4*)(c1 + 4) = make_float4(hi[4], hi[5], hi[6], hi[7]);
    }
}

// ---------------- Wx pad+permute: row j<64 -> Wx[j]; 64+2n -> Wx[64+n](B); 65+2n -> Wx[80+n](C); >=96 -> 0
__global__ void wxpad_kernel(const float* __restrict__ Wx_f, const float* __restrict__ Wx_r)
{
    int idx = blockIdx.x * 256 + threadIdx.x;       // 2*128*2048 = 2^19
    int k = idx & (DI - 1);
    int j = (idx >> 11) & 127;
    int dir = idx >> 18;
    const float* Wx = dir ? Wx_r : Wx_f;
    float v = 0.f;
    if (j < 64) v = Wx[j * DI + k];
    else if (j < 96) {
        int nn = (j - 64) >> 1;
        int src = ((j - 64) & 1) ? (80 + nn) : (64 + nn);
        v = Wx[src * DI + k];
    }
    g_wxpad[idx] = v;
}

// ---------------- depthwise causal conv (K=4) + SiLU ----------------
__global__ void conv_silu_kernel(const float* __restrict__ Wc_f, const float* __restrict__ bc_f,
                                 const float* __restrict__ Wc_r, const float* __restrict__ bc_r)
{
    size_t idx = (size_t)blockIdx.x * 256 + threadIdx.x;   // 4*1024*2048 = 2^23
    int d  = (int)(idx & (DI - 1));
    int l  = (int)((idx >> 11) & (L_SEQ - 1));
    int db = (int)(idx >> 21);
    int dir = db >> 1;
    const float* Wc = dir ? Wc_r : Wc_f;
    const float* bc = dir ? bc_r : bc_f;
    const float4 w = *(const float4*)(Wc + d * 4);
    const float* base = g_xz + (size_t)db * L_SEQ * (2 * DI);
    float acc = bc[d];
    if (l >= 3) acc = fmaf(w.x, base[(size_t)(l - 3) * 4096 + d], acc);
    if (l >= 2) acc = fmaf(w.y, base[(size_t)(l - 2) * 4096 + d], acc);
    if (l >= 1) acc = fmaf(w.z, base[(size_t)(l - 1) * 4096 + d], acc);
    acc = fmaf(w.w, base[(size_t)l * 4096 + d], acc);
    g_xc[idx] = siluf(acc);
}

// ---------------- split-K reduce for x_dbl ----------------
__global__ void reduce_xdbl_kernel()
{
    int idx = blockIdx.x * 256 + threadIdx.x;       // 2*2048*128 = 2^19
    int dir = idx >> 18;
    int off = idx & ((1 << 18) - 1);
    const float* p = g_xdbl_part + (size_t)dir * 8 * (1 << 18) + off;
    float s = 0.f;
    #pragma unroll
    for (int s8 = 0; s8 < 8; s8++) s += p[(size_t)s8 * (1 << 18)];
    g_xdbl[idx] = s;
}

// ---------------- selective scan: warp = 4 channels x (8 lanes x 2 states) ----------------
__global__ void __launch_bounds__(256)
scan_kernel(const float* __restrict__ Alog_f, const float* __restrict__ Alog_r,
            const float* __restrict__ Dsk_f, const float* __restrict__ Dsk_r)
{
    int blk = blockIdx.x;           // 256 blocks: 64 per (dir,b)
    int db = blk >> 6;
    int dir = db >> 1;
    int dbase = (blk & 63) * 32;
    int lane = threadIdx.x & 31;
    int warp = threadIdx.x >> 5;
    int c4 = lane >> 3;
    int j  = lane & 7;              // state-pair index (n = 2j, 2j+1)
    int d = dbase + warp * 4 + c4;

    const float* Al = dir ? Alog_r : Alog_f;
    const float* Ds = dir ? Dsk_r : Dsk_f;
    const float* dtp = g_dt + (size_t)db * (L_SEQ * DI);
    const float* xcp = g_xc + (size_t)db * (L_SEQ * DI);
    const float* xdp = g_xdbl + (size_t)db * (L_SEQ * 128);
    float* yp = g_y + (size_t)db * (L_SEQ * DI);

    const float LOG2E = 1.4426950408889634f;
    float2 Ap = *(const float2*)(Al + d * NSTATE + 2 * j);
    float A0 = -__expf(Ap.x) * LOG2E;
    float A1 = -__expf(Ap.y) * LOG2E;
    float Dk = Ds[d];
    float h0 = 0.f, h1 = 0.f;

    float dt_c = dtp[d];
    float u_c  = xcp[d];
    float4 bc_c = *(const float4*)(xdp + 64 + 4 * j);   // B0,C0,B1,C1

    for (int t = 0; t < L_SEQ; ++t) {
        float dt_n = 0.f, u_n = 0.f; float4 bc_n = bc_c;
        if (t + 1 < L_SEQ) {
            dt_n = dtp[(size_t)(t + 1) * DI + d];
            u_n  = xcp[(size_t)(t + 1) * DI + d];
            bc_n = *(const float4*)(xdp + (size_t)(t + 1) * 128 + 64 + 4 * j);
        }
        float du = dt_c * u_c;
        h0 = fmaf(ex2f(dt_c * A0), h0, du * bc_c.x);
        h1 = fmaf(ex2f(dt_c * A1), h1, du * bc_c.z);
        float p = fmaf(h0, bc_c.y, h1 * bc_c.w);
        p += __shfl_xor_sync(0xffffffffu, p, 1);
        p += __shfl_xor_sync(0xffffffffu, p, 2);
        p += __shfl_xor_sync(0xffffffffu, p, 4);
        if (j == 0) yp[(size_t)t * DI + d] = fmaf(u_c, Dk, p);
        dt_c = dt_n; u_c = u_n; bc_c = bc_n;
    }
}

// ---------------- gating: y *= silu(z) ----------------
__global__ void gate_kernel()
{
    size_t idx = (size_t)blockIdx.x * 256 + threadIdx.x;   // 2^23
    int d  = (int)(idx & (DI - 1));
    int l  = (int)((idx >> 11) & (L_SEQ - 1));
    int db = (int)(idx >> 21);
    float z = g_xz[((size_t)db * L_SEQ + l) * 4096 + DI + d];
    g_y[idx] *= siluf(z);
}

// ---------------- final reduce: sum 4 partial slabs -> out ----------------
__global__ void reduce_out_kernel(float* __restrict__ out)
{
    int idx = blockIdx.x * 256 + threadIdx.x;       // 2048*1024 = 2^21
    const size_t S = (size_t)(BATCH * L_SEQ) * DMODEL;
    const float* p = g_opart + idx;
    out[idx] = (p[0] + p[S]) + (p[2 * S] + p[3 * S]);
}

// ---------------- launch ----------------
extern "C" void kernel_launch(void* const* d_in, const int* in_sizes, int n_in,
                              void* d_out, int out_size)
{
    (void)in_sizes; (void)n_in; (void)out_size;
    const float* x       = (const float*)d_in[0];
    const float* Win_f   = (const float*)d_in[1];
    const float* Wconv_f = (const float*)d_in[2];
    const float* bconv_f = (const float*)d_in[3];
    const float* Wx_f    = (const float*)d_in[4];
    const float* Wdt_f   = (const float*)d_in[5];
    const float* bdt_f   = (const float*)d_in[6];
    const float* Alog_f  = (const float*)d_in[7];
    const float* Dskip_f = (const float*)d_in[8];
    const float* Wout_f  = (const float*)d_in[9];
    const float* Win_r   = (const float*)d_in[10];
    const float* Wconv_r = (const float*)d_in[11];
    const float* bconv_r = (const float*)d_in[12];
    const float* Wx_r    = (const float*)d_in[13];
    const float* Wdt_r   = (const float*)d_in[14];
    const float* bdt_r   = (const float*)d_in[15];
    const float* Alog_r  = (const float*)d_in[16];
    const float* Dskip_r = (const float*)d_in[17];
    const float* Wout_r  = (const float*)d_in[18];
    float* out = (float*)d_out;

    float *xz, *xc, *wxpad, *xdblp, *xdbl, *dt, *y, *opart;
    cudaGetSymbolAddress((void**)&xz,    g_xz);
    cudaGetSymbolAddress((void**)&xc,    g_xc);
    cudaGetSymbolAddress((void**)&wxpad, g_wxpad);
    cudaGetSymbolAddress((void**)&xdblp, g_xdbl_part);
    cudaGetSymbolAddress((void**)&xdbl,  g_xdbl);
    cudaGetSymbolAddress((void**)&dt,    g_dt);
    cudaGetSymbolAddress((void**)&y,     g_y);
    cudaGetSymbolAddress((void**)&opart, g_opart);

    const long long XZ_DIR  = 2LL * L_SEQ * 2 * DI;      // 8388608
    const long long XC_DIR  = 2LL * L_SEQ * DI;          // 4194304
    const long long XDBL_DIR = 2048LL * 128;             // 262144
    const long long OUT_SLAB = 2048LL * DMODEL;          // 2097152

    // 1. pad+permute Wx
    wxpad_kernel<<<(2 * 128 * DI) / 256, 256>>>(Wx_f, Wx_r);

    // 2. in-projection (both dirs; rev handled by A-row remap)
    gemm_f2<<<dim3(32, 16, 1), 256>>>(x, Win_f, xz,          DMODEL, DMODEL, DMODEL, 2 * DI, 0, 0, nullptr, 0);
    gemm_f2<<<dim3(32, 16, 1), 256>>>(x, Win_r, xz + XZ_DIR, DMODEL, DMODEL, DMODEL, 2 * DI, 1, 0, nullptr, 0);

    // 3. depthwise conv + silu
    conv_silu_kernel<<<(4 * L_SEQ * DI) / 256, 256>>>(Wconv_f, bconv_f, Wconv_r, bconv_r);

    // 4. x_dbl = xc @ Wxpad^T   (split-K=8 -> partials -> reduce)
    gemm_f2<<<dim3(1, 16, 8), 256>>>(xc,          wxpad,            xdblp,                256, DI, DI, 128, 0, 0, nullptr, XDBL_DIR);
    gemm_f2<<<dim3(1, 16, 8), 256>>>(xc + XC_DIR, wxpad + 128 * DI, xdblp + 8 * XDBL_DIR, 256, DI, DI, 128, 0, 0, nullptr, XDBL_DIR);
    reduce_xdbl_kernel<<<(2 * 2048 * 128) / 256, 256>>>();

    // 5. dt = softplus(xdbl[:, :64] @ Wdt^T + bdt)
    gemm_f2<<<dim3(16, 16, 1), 256>>>(xdbl,            Wdt_f, dt,          DTRANK, 128, DTRANK, DI, 0, 2, bdt_f, 0);
    gemm_f2<<<dim3(16, 16, 1), 256>>>(xdbl + XDBL_DIR, Wdt_r, dt + XC_DIR, DTRANK, 128, DTRANK, DI, 0, 2, bdt_r, 0);

    // 6. selective scan
    scan_kernel<<<256, 256>>>(Alog_f, Alog_r, Dskip_f, Dskip_r);

    // 7. gating y *= silu(z)
    gate_kernel<<<(4 * L_SEQ * DI) / 256, 256>>>();

    // 8. out-projection (split-K=2 partials; rev reads y_r at reversed rows)
    gemm_f2<<<dim3(8, 16, 2), 256>>>(y,          Wout_f, opart,                1024, DI, DI, DMODEL, 0, 0, nullptr, OUT_SLAB);
    gemm_f2<<<dim3(8, 16, 2), 256>>>(y + XC_DIR, Wout_r, opart + 2 * OUT_SLAB, 1024, DI, DI, DMODEL, 1, 0, nullptr, OUT_SLAB);

    // 9. sum 4 partial slabs -> out
    reduce_out_kernel<<<(2048 * DMODEL) / 256, 256>>>(out);
}

// round 9
// speedup vs baseline: 1.5921x; 1.5695x over previous
#include <cuda_runtime.h>
#include <cuda_bf16.h>
#include <cstdint>

typedef __nv_bfloat16 bf16;

#define L_SEQ   1024
#define BATCH   2
#define DMODEL  1024
#define DI      2048
#define NSTATE  16
#define DTRANK  64

// ---------------- fp32 scratch ----------------
__device__ float g_xz[4u * L_SEQ * 2 * DI];          // [dir*2+b][l][4096] (xi | z), dir-local time
__device__ float g_xc[4u * L_SEQ * DI];              // conv+silu output (u), fp32 for scan
__device__ float g_xdbl[2u * (BATCH*L_SEQ) * 128];   // cols 0..63 dt-rank, 64+2n=B[n], 65+2n=C[n]
__device__ float g_dt[4u * L_SEQ * DI];              // softplus(dt)
__device__ float g_opart[2u * (BATCH*L_SEQ) * DMODEL];

// ---------------- bf16 hi/lo scratch (16B aligned for cp.async) ----------------
__device__ __align__(16) bf16 g_xh[BATCH*L_SEQ*DMODEL],    g_xl[BATCH*L_SEQ*DMODEL];
__device__ __align__(16) bf16 g_Winh[2u*2*DI*DMODEL],      g_Winl[2u*2*DI*DMODEL];
__device__ __align__(16) bf16 g_Wouth[2u*DMODEL*DI],       g_Woutl[2u*DMODEL*DI];
__device__ __align__(16) bf16 g_Wdth[2u*DI*DTRANK],        g_Wdtl[2u*DI*DTRANK];
__device__ __align__(16) bf16 g_wxh[2u*128*DI],            g_wxl[2u*128*DI];
__device__ __align__(16) bf16 g_xch[4u*L_SEQ*DI],          g_xcl[4u*L_SEQ*DI];
__device__ __align__(16) bf16 g_xdh[2u*(BATCH*L_SEQ)*128], g_xdl[2u*(BATCH*L_SEQ)*128];
__device__ __align__(16) bf16 g_yh[4u*L_SEQ*DI],           g_yl[4u*L_SEQ*DI];

// ---------------- helpers ----------------
__device__ __forceinline__ float ex2f(float x) {
    float r; asm("ex2.approx.f32 %0, %1;" : "=f"(r) : "f"(x)); return r;
}
__device__ __forceinline__ float softplusf(float v) {
    return v > 20.f ? v : log1pf(expf(v));
}
__device__ __forceinline__ float siluf(float v) {
    return v / (1.f + __expf(-v));
}
__device__ __forceinline__ uint32_t smem_u32(const void* p) {
    uint32_t a;
    asm("{ .reg .u64 t; cvta.to.shared.u64 t, %1; cvt.u32.u64 %0, t; }" : "=r"(a) : "l"(p));
    return a;
}

#define LDSM_X4(r0, r1, r2, r3, addr)                                              \
    asm volatile("ldmatrix.sync.aligned.m8n8.x4.shared.b16 {%0,%1,%2,%3}, [%4];"   \
                 : "=r"(r0), "=r"(r1), "=r"(r2), "=r"(r3) : "r"(addr))
#define LDSM_X2(r0, r1, addr)                                                      \
    asm volatile("ldmatrix.sync.aligned.m8n8.x2.shared.b16 {%0,%1}, [%2];"         \
                 : "=r"(r0), "=r"(r1) : "r"(addr))
#define MMA16816(d, a, b)                                                          \
    asm volatile("mma.sync.aligned.m16n8k16.row.col.f32.bf16.bf16.f32 "            \
                 "{%0,%1,%2,%3}, {%4,%5,%6,%7}, {%8,%9}, {%0,%1,%2,%3};"           \
                 : "+f"((d)[0]), "+f"((d)[1]), "+f"((d)[2]), "+f"((d)[3])          \
                 : "r"((a)[0]), "r"((a)[1]), "r"((a)[2]), "r"((a)[3]),             \
                   "r"((b)[0]), "r"((b)[1]))

// SMEM: 2 stages x {Ah, Al, Bh, Bl}, each tile 128 rows x 32 bf16, padded stride 40 elts (80B)
#define KSP        40
#define TILE_B     10240          // 128*80
#define STAGE_B    40960          // 4 tiles
#define GEMM_SMEM  81920          // 2 stages

__device__ __forceinline__ void ldtile32(uint32_t sbase, const bf16* g, int ldk,
                                         int row0, int xorm, int kcol, int tid) {
    #pragma unroll
    for (int i = 0; i < 2; i++) {
        int c = i * 256 + tid;            // 512 chunks of 16B
        int row = c >> 2;
        int seg = c & 3;
        int grow = (row0 + row) ^ xorm;
        const char* gp = (const char*)(g + (long long)grow * ldk + kcol + seg * 8);
        uint32_t sa = sbase + (uint32_t)(row * 80 + seg * 16);
        asm volatile("cp.async.ca.shared.global [%0], [%1], 16;" :: "r"(sa), "l"(gp));
    }
}

// ============ bf16-split HMMA GEMM: C[M,N] = A[M,K] @ B[N,K]^T (Ah*Bh + Ah*Bl + Al*Bh) ============
// grid: (N/128, M/128, 2 dirs). revz: xor A row with 1023 when z==1. epi: 0 store; 1 store + bf16
// hi/lo to auxh/auxl; 2 softplus(v + bias[col]).
__global__ void __launch_bounds__(256)
gemm_mma(const bf16* __restrict__ Ah, const bf16* __restrict__ Al,
         const bf16* __restrict__ Bh, const bf16* __restrict__ Bl,
         float* __restrict__ C, int K, int lda, int ldb, int ldc,
         long long aoffz, long long boffz, long long coffz,
         int revz, int epi,
         const float* __restrict__ bias0, const float* __restrict__ bias1,
         bf16* __restrict__ auxh, bf16* __restrict__ auxl, long long auxoffz)
{
    extern __shared__ char smem[];
    const uint32_t sb = smem_u32(smem);
    const int tid = threadIdx.x;
    const int wid = tid >> 5;
    const int lane = tid & 31;
    const int wm = wid >> 1;              // 0..3 -> m offset wm*32
    const int wn = wid & 1;               // 0..1 -> n offset wn*64

    const long long z = blockIdx.z;
    const bf16* ah = Ah + z * aoffz;
    const bf16* al = Al + z * aoffz;
    const bf16* bh = Bh + z * boffz;
    const bf16* bl = Bl + z * boffz;
    const int m0 = blockIdx.y * 128;
    const int n0 = blockIdx.x * 128;
    const int xorm = (revz && z == 1) ? (L_SEQ - 1) : 0;
    const int KT = K >> 5;                // 32-wide chunks

    float acc[2][8][4];
    #pragma unroll
    for (int mt = 0; mt < 2; mt++)
        #pragma unroll
        for (int nt = 0; nt < 8; nt++)
            #pragma unroll
            for (int q = 0; q < 4; q++) acc[mt][nt][q] = 0.f;

    // fragment smem offsets (bytes), relative to tile base
    const uint32_t aOff = (uint32_t)((wm * 32 + (lane & 15)) * KSP + (lane >> 4) * 8) * 2;
    const uint32_t bOff = (uint32_t)((wn * 64 + (lane & 7)) * KSP + ((lane >> 3) & 1) * 8) * 2;

    // prologue: fill stage 0
    ldtile32(sb + 0 * STAGE_B + 0 * TILE_B, ah, lda, m0, xorm, 0, tid);
    ldtile32(sb + 0 * STAGE_B + 1 * TILE_B, al, lda, m0, xorm, 0, tid);
    ldtile32(sb + 0 * STAGE_B + 2 * TILE_B, bh, ldb, n0, 0,    0, tid);
    ldtile32(sb + 0 * STAGE_B + 3 * TILE_B, bl, ldb, n0, 0,    0, tid);
    asm volatile("cp.async.commit_group;" ::: "memory");

    for (int kt = 0; kt < KT; ++kt) {
        if (kt + 1 < KT) {
            uint32_t st = sb + ((kt + 1) & 1) * STAGE_B;
            int kc = (kt + 1) * 32;
            ldtile32(st + 0 * TILE_B, ah, lda, m0, xorm, kc, tid);
            ldtile32(st + 1 * TILE_B, al, lda, m0, xorm, kc, tid);
            ldtile32(st + 2 * TILE_B, bh, ldb, n0, 0,    kc, tid);
            ldtile32(st + 3 * TILE_B, bl, ldb, n0, 0,    kc, tid);
            asm volatile("cp.async.commit_group;" ::: "memory");
            asm volatile("cp.async.wait_group 1;" ::: "memory");
        } else {
            asm volatile("cp.async.wait_group 0;" ::: "memory");
        }
        __syncthreads();

        const uint32_t st = sb + (kt & 1) * STAGE_B;
        const uint32_t sAh = st + 0 * TILE_B + aOff;
        const uint32_t sAl = st + 1 * TILE_B + aOff;
        const uint32_t sBh = st + 2 * TILE_B + bOff;
        const uint32_t sBl = st + 3 * TILE_B + bOff;

        #pragma unroll
        for (int kh = 0; kh < 2; kh++) {
            const uint32_t ko = kh * 32;          // 16 elts * 2B
            uint32_t ahf[2][4], alf[2][4];
            #pragma unroll
            for (int mt = 0; mt < 2; mt++) {
                LDSM_X4(ahf[mt][0], ahf[mt][1], ahf[mt][2], ahf[mt][3],
                        sAh + mt * (16 * KSP * 2) + ko);
                LDSM_X4(alf[mt][0], alf[mt][1], alf[mt][2], alf[mt][3],
                        sAl + mt * (16 * KSP * 2) + ko);
            }
            #pragma unroll
            for (int ng = 0; ng < 2; ng++) {
                uint32_t bhf[4][2], blf[4][2];
                #pragma unroll
                for (int q = 0; q < 4; q++) {
                    int nt = ng * 4 + q;
                    LDSM_X2(bhf[q][0], bhf[q][1], sBh + nt * (8 * KSP * 2) + ko);
                    LDSM_X2(blf[q][0], blf[q][1], sBl + nt * (8 * KSP * 2) + ko);
                }
                #pragma unroll
                for (int mt = 0; mt < 2; mt++)
                    #pragma unroll
                    for (int q = 0; q < 4; q++) {
                        float* d = acc[mt][ng * 4 + q];
                        MMA16816(d, ahf[mt], bhf[q]);
                        MMA16816(d, ahf[mt], blf[q]);
                        MMA16816(d, alf[mt], bhf[q]);
                    }
            }
        }
        __syncthreads();
    }

    // epilogue: c fragment rows (lane>>2, +8), cols (lane&3)*2
    const float* bias = z ? bias1 : bias0;
    #pragma unroll
    for (int mt = 0; mt < 2; mt++) {
        #pragma unroll
        for (int nt = 0; nt < 8; nt++) {
            float* d = acc[mt][nt];
            const int col = n0 + wn * 64 + nt * 8 + (lane & 3) * 2;
            const long long row0 = m0 + wm * 32 + mt * 16 + (lane >> 2);
            if (epi == 2) {
                float b0v = bias[col], b1v = bias[col + 1];
                d[0] = softplusf(d[0] + b0v); d[1] = softplusf(d[1] + b1v);
                d[2] = softplusf(d[2] + b0v); d[3] = softplusf(d[3] + b1v);
            }
            float* c0 = C + z * coffz + row0 * ldc + col;
            float* c1 = c0 + 8LL * ldc;
            *(float2*)c0 = make_float2(d[0], d[1]);
            *(float2*)c1 = make_float2(d[2], d[3]);
            if (epi == 1) {
                bf16* h0 = auxh + z * auxoffz + row0 * ldc + col;
                bf16* l0 = auxl + z * auxoffz + row0 * ldc + col;
                #pragma unroll
                for (int q = 0; q < 4; q++) {
                    bf16 hv = __float2bfloat16(d[q]);
                    bf16 lv = __float2bfloat16(d[q] - __bfloat162float(hv));
                    long long o = (q >> 1) * 8LL * ldc + (q & 1);
                    h0[o] = hv; l0[o] = lv;
                }
            }
        }
    }
}

// ---------------- bf16 hi/lo split ----------------
__global__ void split2(const float* __restrict__ s, bf16* __restrict__ h,
                       bf16* __restrict__ l, int n)
{
    int i = blockIdx.x * 256 + threadIdx.x;
    if (i < n) {
        float v = s[i];
        bf16 a = __float2bfloat16(v);
        h[i] = a;
        l[i] = __float2bfloat16(v - __bfloat162float(a));
    }
}

// ---------------- Wx pad+permute+split: j<64 -> Wx[j]; 64+2n -> B[n]=Wx[64+n]; 65+2n -> C[n]=Wx[80+n]
__global__ void wxpad_split(const float* __restrict__ Wx_f, const float* __restrict__ Wx_r)
{
    int idx = blockIdx.x * 256 + threadIdx.x;       // 2*128*2048 = 2^19
    int k = idx & (DI - 1);
    int j = (idx >> 11) & 127;
    int dir = idx >> 18;
    const float* Wx = dir ? Wx_r : Wx_f;
    float v = 0.f;
    if (j < 64) v = Wx[j * DI + k];
    else if (j < 96) {
        int nn = (j - 64) >> 1;
        int src = ((j - 64) & 1) ? (80 + nn) : (64 + nn);
        v = Wx[src * DI + k];
    }
    bf16 h = __float2bfloat16(v);
    g_wxh[idx] = h;
    g_wxl[idx] = __float2bfloat16(v - __bfloat162float(h));
}

// ---------------- depthwise causal conv (K=4) + SiLU + bf16 split ----------------
__global__ void conv_silu_kernel(const float* __restrict__ Wc_f, const float* __restrict__ bc_f,
                                 const float* __restrict__ Wc_r, const float* __restrict__ bc_r)
{
    size_t idx = (size_t)blockIdx.x * 256 + threadIdx.x;   // 4*1024*2048 = 2^23
    int d  = (int)(idx & (DI - 1));
    int l  = (int)((idx >> 11) & (L_SEQ - 1));
    int db = (int)(idx >> 21);
    int dir = db >> 1;
    const float* Wc = dir ? Wc_r : Wc_f;
    const float* bc = dir ? bc_r : bc_f;
    const float4 w = *(const float4*)(Wc + d * 4);
    const float* base = g_xz + (size_t)db * L_SEQ * (2 * DI);
    float acc = bc[d];
    if (l >= 3) acc = fmaf(w.x, base[(size_t)(l - 3) * 4096 + d], acc);
    if (l >= 2) acc = fmaf(w.y, base[(size_t)(l - 2) * 4096 + d], acc);
    if (l >= 1) acc = fmaf(w.z, base[(size_t)(l - 1) * 4096 + d], acc);
    acc = fmaf(w.w, base[(size_t)l * 4096 + d], acc);
    float v = siluf(acc);
    g_xc[idx] = v;
    bf16 h = __float2bfloat16(v);
    g_xch[idx] = h;
    g_xcl[idx] = __float2bfloat16(v - __bfloat162float(h));
}

// ---------------- selective scan + silu(z) gating + bf16 split of y ----------------
__global__ void __launch_bounds__(256)
scan_kernel(const float* __restrict__ Alog_f, const float* __restrict__ Alog_r,
            const float* __restrict__ Dsk_f, const float* __restrict__ Dsk_r)
{
    int blk = blockIdx.x;           // 256 blocks: 64 per (dir,b)
    int db = blk >> 6;
    int dir = db >> 1;
    int dbase = (blk & 63) * 32;
    int lane = threadIdx.x & 31;
    int warp = threadIdx.x >> 5;
    int c4 = lane >> 3;
    int j  = lane & 7;              // state-pair index (n = 2j, 2j+1)
    int d = dbase + warp * 4 + c4;

    const float* Al = dir ? Alog_r : Alog_f;
    const float* Ds = dir ? Dsk_r : Dsk_f;
    const float* dtp = g_dt + (size_t)db * (L_SEQ * DI);
    const float* xcp = g_xc + (size_t)db * (L_SEQ * DI);
    const float* xdp = g_xdbl + (size_t)db * (L_SEQ * 128);
    const float* zp  = g_xz + (size_t)db * L_SEQ * 4096 + DI + d;
    bf16* yhp = g_yh + (size_t)db * (L_SEQ * DI);
    bf16* ylp = g_yl + (size_t)db * (L_SEQ * DI);

    const float LOG2E = 1.4426950408889634f;
    float2 Ap = *(const float2*)(Al + d * NSTATE + 2 * j);
    float A0 = -__expf(Ap.x) * LOG2E;
    float A1 = -__expf(Ap.y) * LOG2E;
    float Dk = Ds[d];
    float h0 = 0.f, h1 = 0.f;

    float dt_c = dtp[d];
    float u_c  = xcp[d];
    float z_c  = zp[0];
    float4 bc_c = *(const float4*)(xdp + 64 + 4 * j);   // B0,C0,B1,C1

    for (int t = 0; t < L_SEQ; ++t) {
        float dt_n = 0.f, u_n = 0.f, z_n = 0.f; float4 bc_n = bc_c;
        if (t + 1 < L_SEQ) {
            dt_n = dtp[(size_t)(t + 1) * DI + d];
            u_n  = xcp[(size_t)(t + 1) * DI + d];
            z_n  = zp[(size_t)(t + 1) * 4096];
            bc_n = *(const float4*)(xdp + (size_t)(t + 1) * 128 + 64 + 4 * j);
        }
        float du = dt_c * u_c;
        h0 = fmaf(ex2f(dt_c * A0), h0, du * bc_c.x);
        h1 = fmaf(ex2f(dt_c * A1), h1, du * bc_c.z);
        float p = fmaf(h0, bc_c.y, h1 * bc_c.w);
        p += __shfl_xor_sync(0xffffffffu, p, 1);
        p += __shfl_xor_sync(0xffffffffu, p, 2);
        p += __shfl_xor_sync(0xffffffffu, p, 4);
        if (j == 0) {
            float yv = fmaf(u_c, Dk, p) * siluf(z_c);
            bf16 hv = __float2bfloat16(yv);
            yhp[(size_t)t * DI + d] = hv;
            ylp[(size_t)t * DI + d] = __float2bfloat16(yv - __bfloat162float(hv));
        }
        dt_c = dt_n; u_c = u_n; z_c = z_n; bc_c = bc_n;
    }
}

// ---------------- final reduce: sum 2 partial slabs -> out ----------------
__global__ void reduce_out2(float* __restrict__ out)
{
    int idx = blockIdx.x * 256 + threadIdx.x;       // 2048*1024 = 2^21
    const size_t S = (size_t)(BATCH * L_SEQ) * DMODEL;
    out[idx] = g_opart[idx] + g_opart[idx + S];
}

// ---------------- launch ----------------
extern "C" void kernel_launch(void* const* d_in, const int* in_sizes, int n_in,
                              void* d_out, int out_size)
{
    (void)in_sizes; (void)n_in; (void)out_size;
    const float* x       = (const float*)d_in[0];
    const float* Win_f   = (const float*)d_in[1];
    const float* Wconv_f = (const float*)d_in[2];
    const float* bconv_f = (const float*)d_in[3];
    const float* Wx_f    = (const float*)d_in[4];
    const float* Wdt_f   = (const float*)d_in[5];
    const float* bdt_f   = (const float*)d_in[6];
    const float* Alog_f  = (const float*)d_in[7];
    const float* Dskip_f = (const float*)d_in[8];
    const float* Wout_f  = (const float*)d_in[9];
    const float* Win_r   = (const float*)d_in[10];
    const float* Wconv_r = (const float*)d_in[11];
    const float* bconv_r = (const float*)d_in[12];
    const float* Wx_r    = (const float*)d_in[13];
    const float* Wdt_r   = (const float*)d_in[14];
    const float* bdt_r   = (const float*)d_in[15];
    const float* Alog_r  = (const float*)d_in[16];
    const float* Dskip_r = (const float*)d_in[17];
    const float* Wout_r  = (const float*)d_in[18];
    float* out = (float*)d_out;

    cudaFuncSetAttribute(gemm_mma, cudaFuncAttributeMaxDynamicSharedMemorySize, GEMM_SMEM);

    float *xz, *xdbl, *dtb, *opart;
    bf16 *xh, *xl, *winh, *winl, *wouth, *woutl, *wdth, *wdtl, *wxh, *wxl;
    bf16 *xch, *xcl, *xdh, *xdl, *yh, *yl;
    cudaGetSymbolAddress((void**)&xz,    g_xz);
    cudaGetSymbolAddress((void**)&xdbl,  g_xdbl);
    cudaGetSymbolAddress((void**)&dtb,   g_dt);
    cudaGetSymbolAddress((void**)&opart, g_opart);
    cudaGetSymbolAddress((void**)&xh,    g_xh);
    cudaGetSymbolAddress((void**)&xl,    g_xl);
    cudaGetSymbolAddress((void**)&winh,  g_Winh);
    cudaGetSymbolAddress((void**)&winl,  g_Winl);
    cudaGetSymbolAddress((void**)&wouth, g_Wouth);
    cudaGetSymbolAddress((void**)&woutl, g_Woutl);
    cudaGetSymbolAddress((void**)&wdth,  g_Wdth);
    cudaGetSymbolAddress((void**)&wdtl,  g_Wdtl);
    cudaGetSymbolAddress((void**)&wxh,   g_wxh);
    cudaGetSymbolAddress((void**)&wxl,   g_wxl);
    cudaGetSymbolAddress((void**)&xch,   g_xch);
    cudaGetSymbolAddress((void**)&xcl,   g_xcl);
    cudaGetSymbolAddress((void**)&xdh,   g_xdh);
    cudaGetSymbolAddress((void**)&xdl,   g_xdl);
    cudaGetSymbolAddress((void**)&yh,    g_yh);
    cudaGetSymbolAddress((void**)&yl,    g_yl);

    const long long XZ_DIR   = 2LL * L_SEQ * 2 * DI;     // 8388608 (fp32 elts)
    const long long XC_DIR   = 2LL * L_SEQ * DI;         // 4194304
    const long long XDBL_DIR = 2048LL * 128;             // 262144
    const long long WIN_SZ   = 2LL * DI * DMODEL;        // 4194304
    const long long WOUT_SZ  = (long long)DMODEL * DI;   // 2097152
    const long long WDT_SZ   = (long long)DI * DTRANK;   // 131072
    const long long WX_SZ    = 128LL * DI;               // 262144
    const long long OUT_SLAB = 2048LL * DMODEL;          // 2097152

    // 0. bf16 hi/lo splits of inputs & weights
    split2<<<(2048 * 1024) / 256, 256>>>(x, xh, xl, 2048 * 1024);
    split2<<<(int)(WIN_SZ / 256), 256>>>(Win_f, winh, winl, (int)WIN_SZ);
    split2<<<(int)(WIN_SZ / 256), 256>>>(Win_r, winh + WIN_SZ, winl + WIN_SZ, (int)WIN_SZ);
    split2<<<(int)(WOUT_SZ / 256), 256>>>(Wout_f, wouth, woutl, (int)WOUT_SZ);
    split2<<<(int)(WOUT_SZ / 256), 256>>>(Wout_r, wouth + WOUT_SZ, woutl + WOUT_SZ, (int)WOUT_SZ);
    split2<<<(int)(WDT_SZ / 256), 256>>>(Wdt_f, wdth, wdtl, (int)WDT_SZ);
    split2<<<(int)(WDT_SZ / 256), 256>>>(Wdt_r, wdth + WDT_SZ, wdtl + WDT_SZ, (int)WDT_SZ);
    wxpad_split<<<(int)(2 * WX_SZ / 256), 256>>>(Wx_f, Wx_r);

    // 1. in-projection: xz[z] = x(rev?) @ Win[z]^T   (M=2048, N=4096, K=1024)
    gemm_mma<<<dim3(32, 16, 2), 256, GEMM_SMEM>>>(
        xh, xl, winh, winl, xz, DMODEL, DMODEL, DMODEL, 2 * DI,
        0, WIN_SZ, XZ_DIR, 1, 0, nullptr, nullptr, nullptr, nullptr, 0);

    // 2. depthwise conv + silu (+ bf16 split)
    conv_silu_kernel<<<(4 * L_SEQ * DI) / 256, 256>>>(Wconv_f, bconv_f, Wconv_r, bconv_r);

    // 3. x_dbl = xc @ Wxpad^T   (M=2048, N=128, K=2048), epi1 emits bf16 hi/lo
    gemm_mma<<<dim3(1, 16, 2), 256, GEMM_SMEM>>>(
        xch, xcl, wxh, wxl, xdbl, DI, DI, DI, 128,
        XC_DIR, WX_SZ, XDBL_DIR, 0, 1, nullptr, nullptr, xdh, xdl, XDBL_DIR);

    // 4. dt = softplus(xdbl[:, :64] @ Wdt^T + bdt)   (M=2048, N=2048, K=64)
    gemm_mma<<<dim3(16, 16, 2), 256, GEMM_SMEM>>>(
        xdh, xdl, wdth, wdtl, dtb, DTRANK, 128, DTRANK, DI,
        XDBL_DIR, WDT_SZ, XC_DIR, 0, 2, bdt_f, bdt_r, nullptr, nullptr, 0);

    // 5. selective scan (+ silu(z) gate + bf16 split of y)
    scan_kernel<<<256, 256>>>(Alog_f, Alog_r, Dskip_f, Dskip_r);

    // 6. out-projection: opart[z] = y[z](rev?) @ Wout[z]^T   (M=2048, N=1024, K=2048)
    gemm_mma<<<dim3(8, 16, 2), 256, GEMM_SMEM>>>(
        yh, yl, wouth, woutl, opart, DI, DI, DI, DMODEL,
        XC_DIR, WOUT_SZ, OUT_SLAB, 1, 0, nullptr, nullptr, nullptr, nullptr, 0);

    // 7. out = opart_f + opart_r
    reduce_out2<<<(2048 * DMODEL) / 256, 256>>>(out);
}

// round 12
// speedup vs baseline: 1.6778x; 1.0538x over previous
#include <cuda_runtime.h>
#include <cuda_bf16.h>
#include <cstdint>

typedef __nv_bfloat16 bf16;

#define L_SEQ   1024
#define BATCH   2
#define DMODEL  1024
#define DI      2048
#define NSTATE  16
#define DTRANK  64

// ---------------- fp32 scratch ----------------
__device__ float g_xz[4u * L_SEQ * 2 * DI];          // [dir*2+b][l][4096] (xi | z), dir-local time
__device__ float g_xc[4u * L_SEQ * DI];              // conv+silu output (u), fp32 for scan
__device__ float g_xdbl[2u * (BATCH*L_SEQ) * 128];   // cols 0..63 dt-rank, 64+2n=B[n], 65+2n=C[n]
__device__ float g_dt[4u * L_SEQ * DI];              // softplus(dt)
__device__ float g_opart[2u * (BATCH*L_SEQ) * DMODEL]; // out-proj partials; reused as x_dbl split-K scratch

// ---------------- bf16 hi/lo scratch (16B aligned for cp.async) ----------------
__device__ __align__(16) bf16 g_xh[BATCH*L_SEQ*DMODEL],    g_xl[BATCH*L_SEQ*DMODEL];
__device__ __align__(16) bf16 g_Winh[2u*2*DI*DMODEL],      g_Winl[2u*2*DI*DMODEL];
__device__ __align__(16) bf16 g_Wouth[2u*DMODEL*DI],       g_Woutl[2u*DMODEL*DI];
__device__ __align__(16) bf16 g_Wdth[2u*DI*DTRANK],        g_Wdtl[2u*DI*DTRANK];
__device__ __align__(16) bf16 g_wxh[2u*128*DI],            g_wxl[2u*128*DI];
__device__ __align__(16) bf16 g_xch[4u*L_SEQ*DI],          g_xcl[4u*L_SEQ*DI];
__device__ __align__(16) bf16 g_xdh[2u*(BATCH*L_SEQ)*128], g_xdl[2u*(BATCH*L_SEQ)*128];
__device__ __align__(16) bf16 g_yh[4u*L_SEQ*DI],           g_yl[4u*L_SEQ*DI];

// ---------------- helpers ----------------
__device__ __forceinline__ float ex2f(float x) {
    float r; asm("ex2.approx.f32 %0, %1;" : "=f"(r) : "f"(x)); return r;
}
__device__ __forceinline__ float softplusf(float v) {
    return v > 20.f ? v : log1pf(expf(v));
}
__device__ __forceinline__ float siluf(float v) {
    return v / (1.f + __expf(-v));
}
__device__ __forceinline__ uint32_t smem_u32(const void* p) {
    uint32_t a;
    asm("{ .reg .u64 t; cvta.to.shared.u64 t, %1; cvt.u32.u64 %0, t; }" : "=r"(a) : "l"(p));
    return a;
}

#define LDSM_X4(r0, r1, r2, r3, addr)                                              \
    asm volatile("ldmatrix.sync.aligned.m8n8.x4.shared.b16 {%0,%1,%2,%3}, [%4];"   \
                 : "=r"(r0), "=r"(r1), "=r"(r2), "=r"(r3) : "r"(addr))
#define MMA16816(d, a, b)                                                          \
    asm volatile("mma.sync.aligned.m16n8k16.row.col.f32.bf16.bf16.f32 "            \
                 "{%0,%1,%2,%3}, {%4,%5,%6,%7}, {%8,%9}, {%0,%1,%2,%3};"           \
                 : "+f"((d)[0]), "+f"((d)[1]), "+f"((d)[2]), "+f"((d)[3])          \
                 : "r"((a)[0]), "r"((a)[1]), "r"((a)[2]), "r"((a)[3]),             \
                   "r"((b)[0]), "r"((b)[1]))

// SMEM: 4 stages x {Ah, Al, Bh, Bl}; tile = 128 rows x 32 bf16, padded stride 40 elts (80B)
#define KSP        40
#define TILE_B     10240          // 128*80
#define STAGE_B    40960          // 4 tiles
#define GEMM_SMEM  163840         // 4 stages

__device__ __forceinline__ void ldtile32(uint32_t sbase, const bf16* g, int ldk,
                                         int row0, int xorm, int kcol, int tid) {
    #pragma unroll
    for (int i = 0; i < 2; i++) {
        int c = i * 256 + tid;            // 512 chunks of 16B = 8KB data
        int row = c >> 2;
        int seg = c & 3;
        int grow = (row0 + row) ^ xorm;
        const char* gp = (const char*)(g + (long long)grow * ldk + kcol + seg * 8);
        uint32_t sa = sbase + (uint32_t)(row * 80 + seg * 16);
        asm volatile("cp.async.ca.shared.global [%0], [%1], 16;" :: "r"(sa), "l"(gp));
    }
}

__device__ __forceinline__ void ldtile4(uint32_t st, const bf16* ah, const bf16* al,
                                        const bf16* bh, const bf16* bl,
                                        int lda, int ldb, int m0, int n0, int xorm,
                                        int kc, int tid) {
    ldtile32(st + 0 * TILE_B, ah, lda, m0, xorm, kc, tid);
    ldtile32(st + 1 * TILE_B, al, lda, m0, xorm, kc, tid);
    ldtile32(st + 2 * TILE_B, bh, ldb, n0, 0,    kc, tid);
    ldtile32(st + 3 * TILE_B, bl, ldb, n0, 0,    kc, tid);
}

// ============ bf16-split HMMA GEMM: C = A @ B^T (Ah*Bh + Ah*Bl + Al*Bh) ============
// grid: (N/128, M/128, 2*zdiv). dir = z/zdiv, kbase = (z%zdiv)*Ksub. revz: xor A row
// with 1023 when dir==1. epi: 0 store fp32; 2 softplus(v + bias[col]).
// 4-stage cp.async pipeline, 1 __syncthreads per K-chunk.
__global__ void __launch_bounds__(256)
gemm_mma(const bf16* __restrict__ Ah, const bf16* __restrict__ Al,
         const bf16* __restrict__ Bh, const bf16* __restrict__ Bl,
         float* __restrict__ C, int Ksub, int lda, int ldb, int ldc,
         long long aoffz, long long boffz, long long coffz,
         int zdiv, int revz, int epi,
         const float* __restrict__ bias0, const float* __restrict__ bias1)
{
    extern __shared__ char smem[];
    const uint32_t sb = smem_u32(smem);
    const int tid = threadIdx.x;
    const int wid = tid >> 5;
    const int lane = tid & 31;
    const int wm = wid >> 1;              // 0..3 -> m offset wm*32
    const int wn = wid & 1;               // 0..1 -> n offset wn*64

    const int z = blockIdx.z;
    const int dir = z / zdiv;
    const int kbase = (z % zdiv) * Ksub;
    const bf16* ah = Ah + (long long)dir * aoffz + kbase;
    const bf16* al = Al + (long long)dir * aoffz + kbase;
    const bf16* bh = Bh + (long long)dir * boffz + kbase;
    const bf16* bl = Bl + (long long)dir * boffz + kbase;
    const int m0 = blockIdx.y * 128;
    const int n0 = blockIdx.x * 128;
    const int xorm = (revz && dir == 1) ? (L_SEQ - 1) : 0;
    const int KT = Ksub >> 5;             // 32-wide chunks

    float acc[2][8][4];
    #pragma unroll
    for (int mt = 0; mt < 2; mt++)
        #pragma unroll
        for (int nt = 0; nt < 8; nt++)
            #pragma unroll
            for (int q = 0; q < 4; q++) acc[mt][nt][q] = 0.f;

    // fragment smem byte offsets relative to tile base
    const uint32_t aOff = (uint32_t)((wm * 32 + (lane & 15)) * KSP + (lane >> 4) * 8) * 2;
    const uint32_t bOff4 = (uint32_t)((wn * 64 + (lane & 15)) * KSP + (lane >> 4) * 8) * 2;

    // prologue: fill stages 0..2 (always commit, even if empty, for exact group accounting)
    #pragma unroll
    for (int s = 0; s < 3; s++) {
        if (s < KT)
            ldtile4(sb + s * STAGE_B, ah, al, bh, bl, lda, ldb, m0, n0, xorm, s * 32, tid);
        asm volatile("cp.async.commit_group;" ::: "memory");
    }

    for (int kt = 0; kt < KT; ++kt) {
        asm volatile("cp.async.wait_group 2;" ::: "memory");   // group kt complete
        __syncthreads();

        // issue chunk kt+3 into stage (kt+3)&3 == (kt-1)&3 (all warps done with it)
        {
            int kn = kt + 3;
            if (kn < KT)
                ldtile4(sb + (kn & 3) * STAGE_B, ah, al, bh, bl, lda, ldb, m0, n0, xorm,
                        kn * 32, tid);
            asm volatile("cp.async.commit_group;" ::: "memory");
        }

        const uint32_t st = sb + (kt & 3) * STAGE_B;
        const uint32_t sAh = st + 0 * TILE_B + aOff;
        const uint32_t sAl = st + 1 * TILE_B + aOff;
        const uint32_t sBh = st + 2 * TILE_B + bOff4;
        const uint32_t sBl = st + 3 * TILE_B + bOff4;

        #pragma unroll
        for (int kh = 0; kh < 2; kh++) {
            const uint32_t ko = kh * 32;          // 16 elts * 2B
            uint32_t ahf[2][4], alf[2][4];
            #pragma unroll
            for (int mt = 0; mt < 2; mt++) {
                LDSM_X4(ahf[mt][0], ahf[mt][1], ahf[mt][2], ahf[mt][3],
                        sAh + mt * (16 * KSP * 2) + ko);
                LDSM_X4(alf[mt][0], alf[mt][1], alf[mt][2], alf[mt][3],
                        sAl + mt * (16 * KSP * 2) + ko);
            }
            // B via paired x4: r0,r1 = nt,nt+1 (k0-7); r2,r3 = nt,nt+1 (k8-15)
            uint32_t bhf[8][2], blf[8][2];
            #pragma unroll
            for (int ntp = 0; ntp < 4; ntp++) {
                LDSM_X4(bhf[2*ntp][0], bhf[2*ntp+1][0], bhf[2*ntp][1], bhf[2*ntp+1][1],
                        sBh + ntp * (16 * KSP * 2) + ko);
                LDSM_X4(blf[2*ntp][0], blf[2*ntp+1][0], blf[2*ntp][1], blf[2*ntp+1][1],
                        sBl + ntp * (16 * KSP * 2) + ko);
            }
            #pragma unroll
            for (int mt = 0; mt < 2; mt++)
                #pragma unroll
                for (int nt = 0; nt < 8; nt++) {
                    float* d = acc[mt][nt];
                    MMA16816(d, ahf[mt], bhf[nt]);
                    MMA16816(d, ahf[mt], blf[nt]);
                    MMA16816(d, alf[mt], bhf[nt]);
                }
        }
    }

    // epilogue: c fragment rows (lane>>2, +8), cols (lane&3)*2
    const float* bias = dir ? bias1 : bias0;
    #pragma unroll
    for (int mt = 0; mt < 2; mt++) {
        #pragma unroll
        for (int nt = 0; nt < 8; nt++) {
            float* d = acc[mt][nt];
            const int col = n0 + wn * 64 + nt * 8 + (lane & 3) * 2;
            const long long row0 = m0 + wm * 32 + mt * 16 + (lane >> 2);
            if (epi == 2) {
                float b0v = bias[col], b1v = bias[col + 1];
                d[0] = softplusf(d[0] + b0v); d[1] = softplusf(d[1] + b1v);
                d[2] = softplusf(d[2] + b0v); d[3] = softplusf(d[3] + b1v);
            }
            float* c0 = C + (long long)z * coffz + row0 * ldc + col;
            float* c1 = c0 + 8LL * ldc;
            *(float2*)c0 = make_float2(d[0], d[1]);
            *(float2*)c1 = make_float2(d[2], d[3]);
        }
    }
}

// ---------------- fused bf16 hi/lo split of x + all weights (one launch) ----------------
#define SPLIT_TOT 14942208
__global__ void split_all(const float* __restrict__ x,
                          const float* __restrict__ Wif, const float* __restrict__ Wir,
                          const float* __restrict__ Wof, const float* __restrict__ Wor,
                          const float* __restrict__ Wdf, const float* __restrict__ Wdr)
{
    int i = blockIdx.x * 256 + threadIdx.x;
    const float* src; bf16 *dh, *dl; int j;
    if (i < 2097152)        { src = x;   dh = g_xh;              dl = g_xl;              j = i; }
    else if (i < 6291456)   { src = Wif; dh = g_Winh;            dl = g_Winl;            j = i - 2097152; }
    else if (i < 10485760)  { src = Wir; dh = g_Winh + 4194304;  dl = g_Winl + 4194304;  j = i - 6291456; }
    else if (i < 12582912)  { src = Wof; dh = g_Wouth;           dl = g_Woutl;           j = i - 10485760; }
    else if (i < 14680064)  { src = Wor; dh = g_Wouth + 2097152; dl = g_Woutl + 2097152; j = i - 12582912; }
    else if (i < 14811136)  { src = Wdf; dh = g_Wdth;            dl = g_Wdtl;            j = i - 14680064; }
    else                    { src = Wdr; dh = g_Wdth + 131072;   dl = g_Wdtl + 131072;   j = i - 14811136; }
    float v = src[j];
    bf16 h = __float2bfloat16(v);
    dh[j] = h;
    dl[j] = __float2bfloat16(v - __bfloat162float(h));
}

// ---------------- Wx pad+permute+split: j<64 -> Wx[j]; 64+2n -> B[n]=Wx[64+n]; 65+2n -> C[n]=Wx[80+n]
__global__ void wxpad_split(const float* __restrict__ Wx_f, const float* __restrict__ Wx_r)
{
    int idx = blockIdx.x * 256 + threadIdx.x;       // 2*128*2048 = 2^19
    int k = idx & (DI - 1);
    int j = (idx >> 11) & 127;
    int dir = idx >> 18;
    const float* Wx = dir ? Wx_r : Wx_f;
    float v = 0.f;
    if (j < 64) v = Wx[j * DI + k];
    else if (j < 96) {
        int nn = (j - 64) >> 1;
        int src = ((j - 64) & 1) ? (80 + nn) : (64 + nn);
        v = Wx[src * DI + k];
    }
    bf16 h = __float2bfloat16(v);
    g_wxh[idx] = h;
    g_wxl[idx] = __float2bfloat16(v - __bfloat162float(h));
}

// ---------------- depthwise causal conv (K=4) + SiLU + bf16 split, 4 ch/thread ----------------
__global__ void conv_silu4(const float* __restrict__ Wc_f, const float* __restrict__ bc_f,
                           const float* __restrict__ Wc_r, const float* __restrict__ bc_r)
{
    int t = blockIdx.x * 256 + threadIdx.x;     // 2^21 threads
    int dq = (t & 511) << 2;                    // channel base (0..2044, step 4)
    int l  = (t >> 9) & (L_SEQ - 1);
    int db = t >> 19;                           // 0..3
    int dir = db >> 1;
    const float* Wc = dir ? Wc_r : Wc_f;
    const float* bc = dir ? bc_r : bc_f;
    const float* base = g_xz + (size_t)db * (L_SEQ * 2 * DI) + dq;

    float4 w0 = *(const float4*)(Wc + dq * 4);
    float4 w1 = *(const float4*)(Wc + dq * 4 + 4);
    float4 w2 = *(const float4*)(Wc + dq * 4 + 8);
    float4 w3 = *(const float4*)(Wc + dq * 4 + 12);
    float4 bv = *(const float4*)(bc + dq);

    float4 x0 = *(const float4*)(base + (size_t)l * 4096);
    float a0 = fmaf(w0.w, x0.x, bv.x);
    float a1 = fmaf(w1.w, x0.y, bv.y);
    float a2 = fmaf(w2.w, x0.z, bv.z);
    float a3 = fmaf(w3.w, x0.w, bv.w);
    if (l >= 1) {
        float4 xv = *(const float4*)(base + (size_t)(l - 1) * 4096);
        a0 = fmaf(w0.z, xv.x, a0); a1 = fmaf(w1.z, xv.y, a1);
        a2 = fmaf(w2.z, xv.z, a2); a3 = fmaf(w3.z, xv.w, a3);
    }
    if (l >= 2) {
        float4 xv = *(const float4*)(base + (size_t)(l - 2) * 4096);
        a0 = fmaf(w0.y, xv.x, a0); a1 = fmaf(w1.y, xv.y, a1);
        a2 = fmaf(w2.y, xv.z, a2); a3 = fmaf(w3.y, xv.w, a3);
    }
    if (l >= 3) {
        float4 xv = *(const float4*)(base + (size_t)(l - 3) * 4096);
        a0 = fmaf(w0.x, xv.x, a0); a1 = fmaf(w1.x, xv.y, a1);
        a2 = fmaf(w2.x, xv.z, a2); a3 = fmaf(w3.x, xv.w, a3);
    }
    float v0 = siluf(a0), v1 = siluf(a1), v2 = siluf(a2), v3 = siluf(a3);

    size_t o = (size_t)db * (L_SEQ * DI) + (size_t)l * DI + dq;
    *(float4*)(g_xc + o) = make_float4(v0, v1, v2, v3);

    bf16 h0 = __float2bfloat16(v0), h1 = __float2bfloat16(v1);
    bf16 h2 = __float2bfloat16(v2), h3 = __float2bfloat16(v3);
    __nv_bfloat162* hp = (__nv_bfloat162*)(g_xch + o);
    hp[0] = __halves2bfloat162(h0, h1);
    hp[1] = __halves2bfloat162(h2, h3);
    bf16 l0 = __float2bfloat16(v0 - __bfloat162float(h0));
    bf16 l1 = __float2bfloat16(v1 - __bfloat162float(h1));
    bf16 l2 = __float2bfloat16(v2 - __bfloat162float(h2));
    bf16 l3 = __float2bfloat16(v3 - __bfloat162float(h3));
    __nv_bfloat162* lp = (__nv_bfloat162*)(g_xcl + o);
    lp[0] = __halves2bfloat162(l0, l1);
    lp[1] = __halves2bfloat162(l2, l3);
}

// ---------------- x_dbl split-K reduce (sum 4 slabs) + bf16 hi/lo emit ----------------
__global__ void reduce_xdbl4()
{
    int idx = blockIdx.x * 256 + threadIdx.x;   // 2^19
    int dir = idx >> 18;
    int loc = idx & 262143;
    const float* p = g_opart + (size_t)dir * 4 * 262144 + loc;
    float s = (p[0] + p[262144]) + (p[2 * 262144] + p[3 * 262144]);
    g_xdbl[idx] = s;
    bf16 h = __float2bfloat16(s);
    g_xdh[idx] = h;
    g_xdl[idx] = __float2bfloat16(s - __bfloat162float(h));
}

// ---------------- selective scan + silu(z) gating + bf16 split of y ----------------
__global__ void __launch_bounds__(256)
scan_kernel(const float* __restrict__ Alog_f, const float* __restrict__ Alog_r,
            const float* __restrict__ Dsk_f, const float* __restrict__ Dsk_r)
{
    int blk = blockIdx.x;           // 256 blocks: 64 per (dir,b)
    int db = blk >> 6;
    int dir = db >> 1;
    int dbase = (blk & 63) * 32;
    int lane = threadIdx.x & 31;
    int warp = threadIdx.x >> 5;
    int c4 = lane >> 3;
    int j  = lane & 7;              // state-pair index (n = 2j, 2j+1)
    int d = dbase + warp * 4 + c4;

    const float* Al = dir ? Alog_r : Alog_f;
    const float* Ds = dir ? Dsk_r : Dsk_f;
    const float* dtp = g_dt + (size_t)db * (L_SEQ * DI);
    const float* xcp = g_xc + (size_t)db * (L_SEQ * DI);
    const float* xdp = g_xdbl + (size_t)db * (L_SEQ * 128);
    const float* zp  = g_xz + (size_t)db * L_SEQ * 4096 + DI + d;
    bf16* yhp = g_yh + (size_t)db * (L_SEQ * DI);
    bf16* ylp = g_yl + (size_t)db * (L_SEQ * DI);

    const float LOG2E = 1.4426950408889634f;
    float2 Ap = *(const float2*)(Al + d * NSTATE + 2 * j);
    float A0 = -__expf(Ap.x) * LOG2E;
    float A1 = -__expf(Ap.y) * LOG2E;
    float Dk = Ds[d];
    float h0 = 0.f, h1 = 0.f;

    float dt_c = dtp[d];
    float u_c  = xcp[d];
    float z_c  = zp[0];
    float4 bc_c = *(const float4*)(xdp + 64 + 4 * j);   // B0,C0,B1,C1

    for (int t = 0; t < L_SEQ; ++t) {
        float dt_n = 0.f, u_n = 0.f, z_n = 0.f; float4 bc_n = bc_c;
        if (t + 1 < L_SEQ) {
            dt_n = dtp[(size_t)(t + 1) * DI + d];
            u_n  = xcp[(size_t)(t + 1) * DI + d];
            z_n  = zp[(size_t)(t + 1) * 4096];
            bc_n = *(const float4*)(xdp + (size_t)(t + 1) * 128 + 64 + 4 * j);
        }
        float du = dt_c * u_c;
        h0 = fmaf(ex2f(dt_c * A0), h0, du * bc_c.x);
        h1 = fmaf(ex2f(dt_c * A1), h1, du * bc_c.z);
        float p = fmaf(h0, bc_c.y, h1 * bc_c.w);
        p += __shfl_xor_sync(0xffffffffu, p, 1);
        p += __shfl_xor_sync(0xffffffffu, p, 2);
        p += __shfl_xor_sync(0xffffffffu, p, 4);
        if (j == 0) {
            float yv = fmaf(u_c, Dk, p) * siluf(z_c);
            bf16 hv = __float2bfloat16(yv);
            yhp[(size_t)t * DI + d] = hv;
            ylp[(size_t)t * DI + d] = __float2bfloat16(yv - __bfloat162float(hv));
        }
        dt_c = dt_n; u_c = u_n; z_c = z_n; bc_c = bc_n;
    }
}

// ---------------- final reduce: sum 2 partial slabs -> out ----------------
__global__ void reduce_out2(float* __restrict__ out)
{
    int idx = blockIdx.x * 256 + threadIdx.x;       // 2048*1024 = 2^21
    const size_t S = (size_t)(BATCH * L_SEQ) * DMODEL;
    out[idx] = g_opart[idx] + g_opart[idx + S];
}

// ---------------- launch ----------------
extern "C" void kernel_launch(void* const* d_in, const int* in_sizes, int n_in,
                              void* d_out, int out_size)
{
    (void)in_sizes; (void)n_in; (void)out_size;
    const float* x       = (const float*)d_in[0];
    const float* Win_f   = (const float*)d_in[1];
    const float* Wconv_f = (const float*)d_in[2];
    const float* bconv_f = (const float*)d_in[3];
    const float* Wx_f    = (const float*)d_in[4];
    const float* Wdt_f   = (const float*)d_in[5];
    const float* bdt_f   = (const float*)d_in[6];
    const float* Alog_f  = (const float*)d_in[7];
    const float* Dskip_f = (const float*)d_in[8];
    const float* Wout_f  = (const float*)d_in[9];
    const float* Win_r   = (const float*)d_in[10];
    const float* Wconv_r = (const float*)d_in[11];
    const float* bconv_r = (const float*)d_in[12];
    const float* Wx_r    = (const float*)d_in[13];
    const float* Wdt_r   = (const float*)d_in[14];
    const float* bdt_r   = (const float*)d_in[15];
    const float* Alog_r  = (const float*)d_in[16];
    const float* Dskip_r = (const float*)d_in[17];
    const float* Wout_r  = (const float*)d_in[18];
    float* out = (float*)d_out;

    cudaFuncSetAttribute(gemm_mma, cudaFuncAttributeMaxDynamicSharedMemorySize, GEMM_SMEM);

    float *xz, *dtb, *opart;
    bf16 *xh, *xl, *winh, *winl, *wouth, *woutl, *wdth, *wdtl, *wxh, *wxl;
    bf16 *xch, *xcl, *xdh, *xdl, *yh, *yl;
    cudaGetSymbolAddress((void**)&xz,    g_xz);
    cudaGetSymbolAddress((void**)&dtb,   g_dt);
    cudaGetSymbolAddress((void**)&opart, g_opart);
    cudaGetSymbolAddress((void**)&xh,    g_xh);
    cudaGetSymbolAddress((void**)&xl,    g_xl);
    cudaGetSymbolAddress((void**)&winh,  g_Winh);
    cudaGetSymbolAddress((void**)&winl,  g_Winl);
    cudaGetSymbolAddress((void**)&wouth, g_Wouth);
    cudaGetSymbolAddress((void**)&woutl, g_Woutl);
    cudaGetSymbolAddress((void**)&wdth,  g_Wdth);
    cudaGetSymbolAddress((void**)&wdtl,  g_Wdtl);
    cudaGetSymbolAddress((void**)&wxh,   g_wxh);
    cudaGetSymbolAddress((void**)&wxl,   g_wxl);
    cudaGetSymbolAddress((void**)&xch,   g_xch);
    cudaGetSymbolAddress((void**)&xcl,   g_xcl);
    cudaGetSymbolAddress((void**)&xdh,   g_xdh);
    cudaGetSymbolAddress((void**)&xdl,   g_xdl);
    cudaGetSymbolAddress((void**)&yh,    g_yh);
    cudaGetSymbolAddress((void**)&yl,    g_yl);

    const long long XZ_DIR   = 2LL * L_SEQ * 2 * DI;     // 8388608 (fp32 elts)
    const long long XC_DIR   = 2LL * L_SEQ * DI;         // 4194304
    const long long XDBL_DIR = 2048LL * 128;             // 262144
    const long long WIN_SZ   = 2LL * DI * DMODEL;        // 4194304
    const long long WOUT_SZ  = (long long)DMODEL * DI;   // 2097152
    const long long WDT_SZ   = (long long)DI * DTRANK;   // 131072
    const long long WX_SZ    = 128LL * DI;               // 262144
    const long long OUT_SLAB = 2048LL * DMODEL;          // 2097152

    // 0. fused bf16 hi/lo splits + Wx pad/permute/split
    split_all<<<SPLIT_TOT / 256, 256>>>(x, Win_f, Win_r, Wout_f, Wout_r, Wdt_f, Wdt_r);
    wxpad_split<<<(int)(2 * WX_SZ / 256), 256>>>(Wx_f, Wx_r);

    // 1. in-projection: xz[dir] = x(rev?) @ Win[dir]^T   (M=2048, N=4096, K=1024)
    gemm_mma<<<dim3(32, 16, 2), 256, GEMM_SMEM>>>(
        xh, xl, winh, winl, xz, DMODEL, DMODEL, DMODEL, 2 * DI,
        0, WIN_SZ, XZ_DIR, 1, 1, 0, nullptr, nullptr);

    // 2. depthwise conv + silu (+ bf16 split), 4 channels/thread
    conv_silu4<<<(4 * L_SEQ * DI / 4) / 256, 256>>>(Wconv_f, bconv_f, Wconv_r, bconv_r);

    // 3. x_dbl = xc @ Wxpad^T, split-K=4 (M=2048, N=128, K=4x512) -> partials in g_opart
    gemm_mma<<<dim3(1, 16, 8), 256, GEMM_SMEM>>>(
        xch, xcl, wxh, wxl, opart, 512, DI, DI, 128,
        XC_DIR, WX_SZ, XDBL_DIR, 4, 0, 0, nullptr, nullptr);
    reduce_xdbl4<<<(1 << 19) / 256, 256>>>();

    // 4. dt = softplus(xdbl[:, :64] @ Wdt^T + bdt)   (M=2048, N=2048, K=64)
    gemm_mma<<<dim3(16, 16, 2), 256, GEMM_SMEM>>>(
        xdh, xdl, wdth, wdtl, dtb, DTRANK, 128, DTRANK, DI,
        XDBL_DIR, WDT_SZ, XC_DIR, 1, 0, 2, bdt_f, bdt_r);

    // 5. selective scan (+ silu(z) gate + bf16 split of y)
    scan_kernel<<<256, 256>>>(Alog_f, Alog_r, Dskip_f, Dskip_r);

    // 6. out-projection: opart[dir] = y[dir](rev?) @ Wout[dir]^T  (M=2048, N=1024, K=2048)
    gemm_mma<<<dim3(8, 16, 2), 256, GEMM_SMEM>>>(
        yh, yl, wouth, woutl, opart, DI, DI, DI, DMODEL,
        XC_DIR, WOUT_SZ, OUT_SLAB, 1, 1, 0, nullptr, nullptr);

    // 7. out = opart_f + opart_r
    reduce_out2<<<(2048 * DMODEL) / 256, 256>>>(out);
}

// round 14
// speedup vs baseline: 1.8245x; 1.0874x over previous
#include <cuda_runtime.h>
#include <cuda_bf16.h>
#include <cstdint>

typedef __nv_bfloat16 bf16;

#define L_SEQ   1024
#define BATCH   2
#define DMODEL  1024
#define DI      2048
#define NSTATE  16
#define DTRANK  64

// ---------------- fp32 scratch ----------------
__device__ float g_xz[4u * L_SEQ * 2 * DI];          // [dir*2+b][l][4096] (xi | z), dir-local time
__device__ float g_xc[4u * L_SEQ * DI];              // conv+silu output (u), fp32 for scan
__device__ float g_xdbl[2u * (BATCH*L_SEQ) * 128];   // cols 0..63 dt-rank, 64+2n=B[n], 65+2n=C[n]
__device__ float g_dt[4u * L_SEQ * DI];              // softplus(dt)
__device__ float g_opart[2u * (BATCH*L_SEQ) * DMODEL]; // out-proj partials; reused as x_dbl split-K scratch

// ---------------- bf16 hi/lo scratch (16B aligned for cp.async) ----------------
__device__ __align__(16) bf16 g_xh[BATCH*L_SEQ*DMODEL],    g_xl[BATCH*L_SEQ*DMODEL];
__device__ __align__(16) bf16 g_Winh[2u*2*DI*DMODEL],      g_Winl[2u*2*DI*DMODEL];
__device__ __align__(16) bf16 g_Wouth[2u*DMODEL*DI],       g_Woutl[2u*DMODEL*DI];
__device__ __align__(16) bf16 g_Wdth[2u*DI*DTRANK],        g_Wdtl[2u*DI*DTRANK];
__device__ __align__(16) bf16 g_wxh[2u*128*DI],            g_wxl[2u*128*DI];
__device__ __align__(16) bf16 g_xch[4u*L_SEQ*DI],          g_xcl[4u*L_SEQ*DI];
__device__ __align__(16) bf16 g_xdh[2u*(BATCH*L_SEQ)*128], g_xdl[2u*(BATCH*L_SEQ)*128];
__device__ __align__(16) bf16 g_yh[4u*L_SEQ*DI],           g_yl[4u*L_SEQ*DI];

// ---------------- helpers ----------------
__device__ __forceinline__ float ex2f(float x) {
    float r; asm("ex2.approx.f32 %0, %1;" : "=f"(r) : "f"(x)); return r;
}
__device__ __forceinline__ float softplusf(float v) {
    return v > 20.f ? v : log1pf(expf(v));
}
__device__ __forceinline__ float siluf(float v) {
    return v / (1.f + __expf(-v));
}
__device__ __forceinline__ uint32_t smem_u32(const void* p) {
    uint32_t a;
    asm("{ .reg .u64 t; cvta.to.shared.u64 t, %1; cvt.u32.u64 %0, t; }" : "=r"(a) : "l"(p));
    return a;
}

#define LDSM_X4(r0, r1, r2, r3, addr)                                              \
    asm volatile("ldmatrix.sync.aligned.m8n8.x4.shared.b16 {%0,%1,%2,%3}, [%4];"   \
                 : "=r"(r0), "=r"(r1), "=r"(r2), "=r"(r3) : "r"(addr))
#define MMA16816(d, a, b)                                                          \
    asm volatile("mma.sync.aligned.m16n8k16.row.col.f32.bf16.bf16.f32 "            \
                 "{%0,%1,%2,%3}, {%4,%5,%6,%7}, {%8,%9}, {%0,%1,%2,%3};"           \
                 : "+f"((d)[0]), "+f"((d)[1]), "+f"((d)[2]), "+f"((d)[3])          \
                 : "r"((a)[0]), "r"((a)[1]), "r"((a)[2]), "r"((a)[3]),             \
                   "r"((b)[0]), "r"((b)[1]))

// SMEM: 2 stages x {Ah, Al, Bh, Bl}; tile = 128 rows x 32 bf16, padded stride 40 elts (80B)
#define KSP        40
#define TILE_B     10240          // 128*80
#define STAGE_B    40960          // 4 tiles
#define GEMM_SMEM  81920          // 2 stages -> 2 CTAs/SM

__device__ __forceinline__ void ldtile32(uint32_t sbase, const bf16* g, int ldk,
                                         int row0, int xorm, int kcol, int tid) {
    #pragma unroll
    for (int i = 0; i < 2; i++) {
        int c = i * 256 + tid;            // 512 chunks of 16B = 8KB data
        int row = c >> 2;
        int seg = c & 3;
        int grow = (row0 + row) ^ xorm;
        const char* gp = (const char*)(g + (long long)grow * ldk + kcol + seg * 8);
        uint32_t sa = sbase + (uint32_t)(row * 80 + seg * 16);
        asm volatile("cp.async.ca.shared.global [%0], [%1], 16;" :: "r"(sa), "l"(gp));
    }
}

__device__ __forceinline__ void ldtile4(uint32_t st, const bf16* ah, const bf16* al,
                                        const bf16* bh, const bf16* bl,
                                        int lda, int ldb, int m0, int n0, int xorm,
                                        int kc, int tid) {
    ldtile32(st + 0 * TILE_B, ah, lda, m0, xorm, kc, tid);
    ldtile32(st + 1 * TILE_B, al, lda, m0, xorm, kc, tid);
    ldtile32(st + 2 * TILE_B, bh, ldb, n0, 0,    kc, tid);
    ldtile32(st + 3 * TILE_B, bl, ldb, n0, 0,    kc, tid);
}

// ============ bf16-split HMMA GEMM: C = A @ B^T (Ah*Bh + Ah*Bl + Al*Bh) ============
// grid: (N/128, M/128, 2*zdiv). dir = z/zdiv, kbase = (z%zdiv)*Ksub. revz: xor A row
// with 1023 when dir==1. epi: 0 store fp32; 2 softplus(v + bias[col]).
// 2-stage cp.async pipeline, 1 __syncthreads per K-chunk, 2 CTAs/SM.
__global__ void __launch_bounds__(256, 2)
gemm_mma(const bf16* __restrict__ Ah, const bf16* __restrict__ Al,
         const bf16* __restrict__ Bh, const bf16* __restrict__ Bl,
         float* __restrict__ C, int Ksub, int lda, int ldb, int ldc,
         long long aoffz, long long boffz, long long coffz,
         int zdiv, int revz, int epi,
         const float* __restrict__ bias0, const float* __restrict__ bias1)
{
    extern __shared__ char smem[];
    const uint32_t sb = smem_u32(smem);
    const int tid = threadIdx.x;
    const int wid = tid >> 5;
    const int lane = tid & 31;
    const int wm = wid >> 1;              // 0..3 -> m offset wm*32
    const int wn = wid & 1;               // 0..1 -> n offset wn*64

    const int z = blockIdx.z;
    const int dir = z / zdiv;
    const int kbase = (z % zdiv) * Ksub;
    const bf16* ah = Ah + (long long)dir * aoffz + kbase;
    const bf16* al = Al + (long long)dir * aoffz + kbase;
    const bf16* bh = Bh + (long long)dir * boffz + kbase;
    const bf16* bl = Bl + (long long)dir * boffz + kbase;
    const int m0 = blockIdx.y * 128;
    const int n0 = blockIdx.x * 128;
    const int xorm = (revz && dir == 1) ? (L_SEQ - 1) : 0;
    const int KT = Ksub >> 5;             // 32-wide chunks

    float acc[2][8][4];
    #pragma unroll
    for (int mt = 0; mt < 2; mt++)
        #pragma unroll
        for (int nt = 0; nt < 8; nt++)
            #pragma unroll
            for (int q = 0; q < 4; q++) acc[mt][nt][q] = 0.f;

    // fragment smem byte offsets relative to tile base
    const uint32_t aOff = (uint32_t)((wm * 32 + (lane & 15)) * KSP + (lane >> 4) * 8) * 2;
    const uint32_t bOff4 = (uint32_t)((wn * 64 + (lane & 15)) * KSP + (lane >> 4) * 8) * 2;

    // prologue: fill stage 0
    ldtile4(sb, ah, al, bh, bl, lda, ldb, m0, n0, xorm, 0, tid);
    asm volatile("cp.async.commit_group;" ::: "memory");

    for (int kt = 0; kt < KT; ++kt) {
        asm volatile("cp.async.wait_group 0;" ::: "memory");   // all issued groups done
        __syncthreads();                                        // data visible; prior reads drained

        // issue chunk kt+1 into stage (kt+1)&1 (stage of kt-1, proven drained by sync)
        if (kt + 1 < KT) {
            ldtile4(sb + ((kt + 1) & 1) * STAGE_B, ah, al, bh, bl, lda, ldb, m0, n0, xorm,
                    (kt + 1) * 32, tid);
            asm volatile("cp.async.commit_group;" ::: "memory");
        }

        const uint32_t st = sb + (kt & 1) * STAGE_B;
        const uint32_t sAh = st + 0 * TILE_B + aOff;
        const uint32_t sAl = st + 1 * TILE_B + aOff;
        const uint32_t sBh = st + 2 * TILE_B + bOff4;
        const uint32_t sBl = st + 3 * TILE_B + bOff4;

        #pragma unroll
        for (int kh = 0; kh < 2; kh++) {
            const uint32_t ko = kh * 32;          // 16 elts * 2B
            uint32_t ahf[2][4], alf[2][4];
            #pragma unroll
            for (int mt = 0; mt < 2; mt++) {
                LDSM_X4(ahf[mt][0], ahf[mt][1], ahf[mt][2], ahf[mt][3],
                        sAh + mt * (16 * KSP * 2) + ko);
                LDSM_X4(alf[mt][0], alf[mt][1], alf[mt][2], alf[mt][3],
                        sAl + mt * (16 * KSP * 2) + ko);
            }
            // B via paired x4, two nt-groups of 4 to cap live registers (<=128/thread)
            #pragma unroll
            for (int ng = 0; ng < 2; ng++) {
                uint32_t bhf[4][2], blf[4][2];
                #pragma unroll
                for (int ntp = 0; ntp < 2; ntp++) {
                    int base = ng * 2 + ntp;      // pair index among 4
                    LDSM_X4(bhf[2*ntp][0], bhf[2*ntp+1][0], bhf[2*ntp][1], bhf[2*ntp+1][1],
                            sBh + base * (16 * KSP * 2) + ko);
                    LDSM_X4(blf[2*ntp][0], blf[2*ntp+1][0], blf[2*ntp][1], blf[2*ntp+1][1],
                            sBl + base * (16 * KSP * 2) + ko);
                }
                #pragma unroll
                for (int mt = 0; mt < 2; mt++)
                    #pragma unroll
                    for (int q = 0; q < 4; q++) {
                        float* d = acc[mt][ng * 4 + q];
                        MMA16816(d, ahf[mt], bhf[q]);
                        MMA16816(d, ahf[mt], blf[q]);
                        MMA16816(d, alf[mt], bhf[q]);
                    }
            }
        }
    }

    // epilogue: c fragment rows (lane>>2, +8), cols (lane&3)*2
    const float* bias = dir ? bias1 : bias0;
    #pragma unroll
    for (int mt = 0; mt < 2; mt++) {
        #pragma unroll
        for (int nt = 0; nt < 8; nt++) {
            float* d = acc[mt][nt];
            const int col = n0 + wn * 64 + nt * 8 + (lane & 3) * 2;
            const long long row0 = m0 + wm * 32 + mt * 16 + (lane >> 2);
            if (epi == 2) {
                float b0v = bias[col], b1v = bias[col + 1];
                d[0] = softplusf(d[0] + b0v); d[1] = softplusf(d[1] + b1v);
                d[2] = softplusf(d[2] + b0v); d[3] = softplusf(d[3] + b1v);
            }
            float* c0 = C + (long long)z * coffz + row0 * ldc + col;
            float* c1 = c0 + 8LL * ldc;
            *(float2*)c0 = make_float2(d[0], d[1]);
            *(float2*)c1 = make_float2(d[2], d[3]);
        }
    }
}

// ---------------- fused bf16 hi/lo split of x + all weights (one launch) ----------------
#define SPLIT_TOT 14942208
__global__ void split_all(const float* __restrict__ x,
                          const float* __restrict__ Wif, const float* __restrict__ Wir,
                          const float* __restrict__ Wof, const float* __restrict__ Wor,
                          const float* __restrict__ Wdf, const float* __restrict__ Wdr)
{
    int i = blockIdx.x * 256 + threadIdx.x;
    const float* src; bf16 *dh, *dl; int j;
    if (i < 2097152)        { src = x;   dh = g_xh;              dl = g_xl;              j = i; }
    else if (i < 6291456)   { src = Wif; dh = g_Winh;            dl = g_Winl;            j = i - 2097152; }
    else if (i < 10485760)  { src = Wir; dh = g_Winh + 4194304;  dl = g_Winl + 4194304;  j = i - 6291456; }
    else if (i < 12582912)  { src = Wof; dh = g_Wouth;           dl = g_Woutl;           j = i - 10485760; }
    else if (i < 14680064)  { src = Wor; dh = g_Wouth + 2097152; dl = g_Woutl + 2097152; j = i - 12582912; }
    else if (i < 14811136)  { src = Wdf; dh = g_Wdth;            dl = g_Wdtl;            j = i - 14680064; }
    else                    { src = Wdr; dh = g_Wdth + 131072;   dl = g_Wdtl + 131072;   j = i - 14811136; }
    float v = src[j];
    bf16 h = __float2bfloat16(v);
    dh[j] = h;
    dl[j] = __float2bfloat16(v - __bfloat162float(h));
}

// ---------------- Wx pad+permute+split: j<64 -> Wx[j]; 64+2n -> B[n]=Wx[64+n]; 65+2n -> C[n]=Wx[80+n]
__global__ void wxpad_split(const float* __restrict__ Wx_f, const float* __restrict__ Wx_r)
{
    int idx = blockIdx.x * 256 + threadIdx.x;       // 2*128*2048 = 2^19
    int k = idx & (DI - 1);
    int j = (idx >> 11) & 127;
    int dir = idx >> 18;
    const float* Wx = dir ? Wx_r : Wx_f;
    float v = 0.f;
    if (j < 64) v = Wx[j * DI + k];
    else if (j < 96) {
        int nn = (j - 64) >> 1;
        int src = ((j - 64) & 1) ? (80 + nn) : (64 + nn);
        v = Wx[src * DI + k];
    }
    bf16 h = __float2bfloat16(v);
    g_wxh[idx] = h;
    g_wxl[idx] = __float2bfloat16(v - __bfloat162float(h));
}

// ---------------- depthwise causal conv (K=4) + SiLU + bf16 split, 4 ch/thread ----------------
__global__ void conv_silu4(const float* __restrict__ Wc_f, const float* __restrict__ bc_f,
                           const float* __restrict__ Wc_r, const float* __restrict__ bc_r)
{
    int t = blockIdx.x * 256 + threadIdx.x;     // 2^21 threads
    int dq = (t & 511) << 2;                    // channel base (0..2044, step 4)
    int l  = (t >> 9) & (L_SEQ - 1);
    int db = t >> 19;                           // 0..3
    int dir = db >> 1;
    const float* Wc = dir ? Wc_r : Wc_f;
    const float* bc = dir ? bc_r : bc_f;
    const float* base = g_xz + (size_t)db * (L_SEQ * 2 * DI) + dq;

    float4 w0 = *(const float4*)(Wc + dq * 4);
    float4 w1 = *(const float4*)(Wc + dq * 4 + 4);
    float4 w2 = *(const float4*)(Wc + dq * 4 + 8);
    float4 w3 = *(const float4*)(Wc + dq * 4 + 12);
    float4 bv = *(const float4*)(bc + dq);

    float4 x0 = *(const float4*)(base + (size_t)l * 4096);
    float a0 = fmaf(w0.w, x0.x, bv.x);
    float a1 = fmaf(w1.w, x0.y, bv.y);
    float a2 = fmaf(w2.w, x0.z, bv.z);
    float a3 = fmaf(w3.w, x0.w, bv.w);
    if (l >= 1) {
        float4 xv = *(const float4*)(base + (size_t)(l - 1) * 4096);
        a0 = fmaf(w0.z, xv.x, a0); a1 = fmaf(w1.z, xv.y, a1);
        a2 = fmaf(w2.z, xv.z, a2); a3 = fmaf(w3.z, xv.w, a3);
    }
    if (l >= 2) {
        float4 xv = *(const float4*)(base + (size_t)(l - 2) * 4096);
        a0 = fmaf(w0.y, xv.x, a0); a1 = fmaf(w1.y, xv.y, a1);
        a2 = fmaf(w2.y, xv.z, a2); a3 = fmaf(w3.y, xv.w, a3);
    }
    if (l >= 3) {
        float4 xv = *(const float4*)(base + (size_t)(l - 3) * 4096);
        a0 = fmaf(w0.x, xv.x, a0); a1 = fmaf(w1.x, xv.y, a1);
        a2 = fmaf(w2.x, xv.z, a2); a3 = fmaf(w3.x, xv.w, a3);
    }
    float v0 = siluf(a0), v1 = siluf(a1), v2 = siluf(a2), v3 = siluf(a3);

    size_t o = (size_t)db * (L_SEQ * DI) + (size_t)l * DI + dq;
    *(float4*)(g_xc + o) = make_float4(v0, v1, v2, v3);

    bf16 h0 = __float2bfloat16(v0), h1 = __float2bfloat16(v1);
    bf16 h2 = __float2bfloat16(v2), h3 = __float2bfloat16(v3);
    __nv_bfloat162* hp = (__nv_bfloat162*)(g_xch + o);
    hp[0] = __halves2bfloat162(h0, h1);
    hp[1] = __halves2bfloat162(h2, h3);
    bf16 l0 = __float2bfloat16(v0 - __bfloat162float(h0));
    bf16 l1 = __float2bfloat16(v1 - __bfloat162float(h1));
    bf16 l2 = __float2bfloat16(v2 - __bfloat162float(h2));
    bf16 l3 = __float2bfloat16(v3 - __bfloat162float(h3));
    __nv_bfloat162* lp = (__nv_bfloat162*)(g_xcl + o);
    lp[0] = __halves2bfloat162(l0, l1);
    lp[1] = __halves2bfloat162(l2, l3);
}

// ---------------- x_dbl split-K reduce (sum 4 slabs) + bf16 hi/lo emit ----------------
__global__ void reduce_xdbl4()
{
    int idx = blockIdx.x * 256 + threadIdx.x;   // 2^19
    int dir = idx >> 18;
    int loc = idx & 262143;
    const float* p = g_opart + (size_t)dir * 4 * 262144 + loc;
    float s = (p[0] + p[262144]) + (p[2 * 262144] + p[3 * 262144]);
    g_xdbl[idx] = s;
    bf16 h = __float2bfloat16(s);
    g_xdh[idx] = h;
    g_xdl[idx] = __float2bfloat16(s - __bfloat162float(h));
}

// ---------------- selective scan + silu(z) gating + bf16 split of y ----------------
__global__ void __launch_bounds__(256)
scan_kernel(const float* __restrict__ Alog_f, const float* __restrict__ Alog_r,
            const float* __restrict__ Dsk_f, const float* __restrict__ Dsk_r)
{
    int blk = blockIdx.x;           // 256 blocks: 64 per (dir,b)
    int db = blk >> 6;
    int dir = db >> 1;
    int dbase = (blk & 63) * 32;
    int lane = threadIdx.x & 31;
    int warp = threadIdx.x >> 5;
    int c4 = lane >> 3;
    int j  = lane & 7;              // state-pair index (n = 2j, 2j+1)
    int d = dbase + warp * 4 + c4;

    const float* Al = dir ? Alog_r : Alog_f;
    const float* Ds = dir ? Dsk_r : Dsk_f;
    const float* dtp = g_dt + (size_t)db * (L_SEQ * DI);
    const float* xcp = g_xc + (size_t)db * (L_SEQ * DI);
    const float* xdp = g_xdbl + (size_t)db * (L_SEQ * 128);
    const float* zp  = g_xz + (size_t)db * L_SEQ * 4096 + DI + d;
    bf16* yhp = g_yh + (size_t)db * (L_SEQ * DI);
    bf16* ylp = g_yl + (size_t)db * (L_SEQ * DI);

    const float LOG2E = 1.4426950408889634f;
    float2 Ap = *(const float2*)(Al + d * NSTATE + 2 * j);
    float A0 = -__expf(Ap.x) * LOG2E;
    float A1 = -__expf(Ap.y) * LOG2E;
    float Dk = Ds[d];
    float h0 = 0.f, h1 = 0.f;

    float dt_c = dtp[d];
    float u_c  = xcp[d];
    float z_c  = zp[0];
    float4 bc_c = *(const float4*)(xdp + 64 + 4 * j);   // B0,C0,B1,C1

    for (int t = 0; t < L_SEQ; ++t) {
        float dt_n = 0.f, u_n = 0.f, z_n = 0.f; float4 bc_n = bc_c;
        if (t + 1 < L_SEQ) {
            dt_n = dtp[(size_t)(t + 1) * DI + d];
            u_n  = xcp[(size_t)(t + 1) * DI + d];
            z_n  = zp[(size_t)(t + 1) * 4096];
            bc_n = *(const float4*)(xdp + (size_t)(t + 1) * 128 + 64 + 4 * j);
        }
        float du = dt_c * u_c;
        h0 = fmaf(ex2f(dt_c * A0), h0, du * bc_c.x);
        h1 = fmaf(ex2f(dt_c * A1), h1, du * bc_c.z);
        float p = fmaf(h0, bc_c.y, h1 * bc_c.w);
        p += __shfl_xor_sync(0xffffffffu, p, 1);
        p += __shfl_xor_sync(0xffffffffu, p, 2);
        p += __shfl_xor_sync(0xffffffffu, p, 4);
        if (j == 0) {
            float yv = fmaf(u_c, Dk, p) * siluf(z_c);
            bf16 hv = __float2bfloat16(yv);
            yhp[(size_t)t * DI + d] = hv;
            ylp[(size_t)t * DI + d] = __float2bfloat16(yv - __bfloat162float(hv));
        }
        dt_c = dt_n; u_c = u_n; z_c = z_n; bc_c = bc_n;
    }
}

// ---------------- final reduce: sum 2 partial slabs -> out (float4) ----------------
__global__ void reduce_out2(float* __restrict__ out)
{
    int idx = blockIdx.x * 256 + threadIdx.x;       // 2^19 float4s
    const size_t S4 = (size_t)(BATCH * L_SEQ) * DMODEL / 4;
    const float4* p = (const float4*)g_opart;
    float4 a = p[idx], b = p[idx + S4];
    ((float4*)out)[idx] = make_float4(a.x + b.x, a.y + b.y, a.z + b.z, a.w + b.w);
}

// ---------------- launch ----------------
extern "C" void kernel_launch(void* const* d_in, const int* in_sizes, int n_in,
                              void* d_out, int out_size)
{
    (void)in_sizes; (void)n_in; (void)out_size;
    const float* x       = (const float*)d_in[0];
    const float* Win_f   = (const float*)d_in[1];
    const float* Wconv_f = (const float*)d_in[2];
    const float* bconv_f = (const float*)d_in[3];
    const float* Wx_f    = (const float*)d_in[4];
    const float* Wdt_f   = (const float*)d_in[5];
    const float* bdt_f   = (const float*)d_in[6];
    const float* Alog_f  = (const float*)d_in[7];
    const float* Dskip_f = (const float*)d_in[8];
    const float* Wout_f  = (const float*)d_in[9];
    const float* Win_r   = (const float*)d_in[10];
    const float* Wconv_r = (const float*)d_in[11];
    const float* bconv_r = (const float*)d_in[12];
    const float* Wx_r    = (const float*)d_in[13];
    const float* Wdt_r   = (const float*)d_in[14];
    const float* bdt_r   = (const float*)d_in[15];
    const float* Alog_r  = (const float*)d_in[16];
    const float* Dskip_r = (const float*)d_in[17];
    const float* Wout_r  = (const float*)d_in[18];
    float* out = (float*)d_out;

    cudaFuncSetAttribute(gemm_mma, cudaFuncAttributeMaxDynamicSharedMemorySize, GEMM_SMEM);

    float *xz, *dtb, *opart;
    bf16 *xh, *xl, *winh, *winl, *wouth, *woutl, *wdth, *wdtl, *wxh, *wxl;
    bf16 *xch, *xcl, *xdh, *xdl, *yh, *yl;
    cudaGetSymbolAddress((void**)&xz,    g_xz);
    cudaGetSymbolAddress((void**)&dtb,   g_dt);
    cudaGetSymbolAddress((void**)&opart, g_opart);
    cudaGetSymbolAddress((void**)&xh,    g_xh);
    cudaGetSymbolAddress((void**)&xl,    g_xl);
    cudaGetSymbolAddress((void**)&winh,  g_Winh);
    cudaGetSymbolAddress((void**)&winl,  g_Winl);
    cudaGetSymbolAddress((void**)&wouth, g_Wouth);
    cudaGetSymbolAddress((void**)&woutl, g_Woutl);
    cudaGetSymbolAddress((void**)&wdth,  g_Wdth);
    cudaGetSymbolAddress((void**)&wdtl,  g_Wdtl);
    cudaGetSymbolAddress((void**)&wxh,   g_wxh);
    cudaGetSymbolAddress((void**)&wxl,   g_wxl);
    cudaGetSymbolAddress((void**)&xch,   g_xch);
    cudaGetSymbolAddress((void**)&xcl,   g_xcl);
    cudaGetSymbolAddress((void**)&xdh,   g_xdh);
    cudaGetSymbolAddress((void**)&xdl,   g_xdl);
    cudaGetSymbolAddress((void**)&yh,    g_yh);
    cudaGetSymbolAddress((void**)&yl,    g_yl);

    const long long XZ_DIR   = 2LL * L_SEQ * 2 * DI;     // 8388608 (fp32 elts)
    const long long XC_DIR   = 2LL * L_SEQ * DI;         // 4194304
    const long long XDBL_DIR = 2048LL * 128;             // 262144
    const long long WIN_SZ   = 2LL * DI * DMODEL;        // 4194304
    const long long WOUT_SZ  = (long long)DMODEL * DI;   // 2097152
    const long long WDT_SZ   = (long long)DI * DTRANK;   // 131072
    const long long WX_SZ    = 128LL * DI;               // 262144
    const long long OUT_SLAB = 2048LL * DMODEL;          // 2097152

    // 0. fused bf16 hi/lo splits + Wx pad/permute/split
    split_all<<<SPLIT_TOT / 256, 256>>>(x, Win_f, Win_r, Wout_f, Wout_r, Wdt_f, Wdt_r);
    wxpad_split<<<(int)(2 * WX_SZ / 256), 256>>>(Wx_f, Wx_r);

    // 1. in-projection: xz[dir] = x(rev?) @ Win[dir]^T   (M=2048, N=4096, K=1024)
    gemm_mma<<<dim3(32, 16, 2), 256, GEMM_SMEM>>>(
        xh, xl, winh, winl, xz, DMODEL, DMODEL, DMODEL, 2 * DI,
        0, WIN_SZ, XZ_DIR, 1, 1, 0, nullptr, nullptr);

    // 2. depthwise conv + silu (+ bf16 split), 4 channels/thread
    conv_silu4<<<(4 * L_SEQ * DI / 4) / 256, 256>>>(Wconv_f, bconv_f, Wconv_r, bconv_r);

    // 3. x_dbl = xc @ Wxpad^T, split-K=4 (M=2048, N=128, K=4x512) -> partials in g_opart
    gemm_mma<<<dim3(1, 16, 8), 256, GEMM_SMEM>>>(
        xch, xcl, wxh, wxl, opart, 512, DI, DI, 128,
        XC_DIR, WX_SZ, XDBL_DIR, 4, 0, 0, nullptr, nullptr);
    reduce_xdbl4<<<(1 << 19) / 256, 256>>>();

    // 4. dt = softplus(xdbl[:, :64] @ Wdt^T + bdt)   (M=2048, N=2048, K=64)
    gemm_mma<<<dim3(16, 16, 2), 256, GEMM_SMEM>>>(
        xdh, xdl, wdth, wdtl, dtb, DTRANK, 128, DTRANK, DI,
        XDBL_DIR, WDT_SZ, XC_DIR, 1, 0, 2, bdt_f, bdt_r);

    // 5. selective scan (+ silu(z) gate + bf16 split of y)
    scan_kernel<<<256, 256>>>(Alog_f, Alog_r, Dskip_f, Dskip_r);

    // 6. out-projection: opart[dir] = y[dir](rev?) @ Wout[dir]^T  (M=2048, N=1024, K=2048)
    gemm_mma<<<dim3(8, 16, 2), 256, GEMM_SMEM>>>(
        yh, yl, wouth, woutl, opart, DI, DI, DI, DMODEL,
        XC_DIR, WOUT_SZ, OUT_SLAB, 1, 1, 0, nullptr, nullptr);

    // 7. out = opart_f + opart_r
    reduce_out2<<<(1 << 19) / 256, 256>>>(out);
}